// round 1
// baseline (speedup 1.0000x reference)
#include <cuda_runtime.h>
#include <math.h>

#define B_SZ 4
#define SEQ  2048
#define DIM  1024
#define HEADS 16
#define HD   64
#define HID  4096
#define MROWS (B_SZ*SEQ)   /* 8192 */
#define QKVN  (3*DIM)      /* 3072 */

// ---------------- scratch (static device globals; no runtime alloc) --------
__device__ float g_qkv [(size_t)MROWS*QKVN];
__device__ float g_attn[(size_t)MROWS*DIM];
__device__ float g_x1  [(size_t)MROWS*DIM];
__device__ float g_tmp [(size_t)MROWS*DIM];
__device__ float g_h   [(size_t)MROWS*HID];

// ---------------- SGEMM: C[M,N] = A[M,K] @ B[N,K]^T (+bias)(+PReLU) --------
// 128x128 tile, BK=16, 256 threads, 8x8 microtile. Operands stored k-major
// (transposed) in smem so inner loop is 4x LDS.128 + 64 FFMA per k.
__global__ __launch_bounds__(256) void sgemm_nt(
    const float* __restrict__ A, const float* __restrict__ Bw,
    const float* __restrict__ bias, const float* __restrict__ prelu,
    float* __restrict__ C, int M, int N, int K)
{
    const int tid = threadIdx.x;
    const int tx = tid & 15;          // 16 -> 8 cols each
    const int ty = tid >> 4;          // 16 -> 8 rows each
    const int m0 = blockIdx.y * 128;
    const int n0 = blockIdx.x * 128;

    __shared__ float As[16][132];     // [k][row], padded stride (16B aligned)
    __shared__ float Bs[16][132];     // [k][col]

    float acc[8][8];
#pragma unroll
    for (int i = 0; i < 8; i++)
#pragma unroll
        for (int j = 0; j < 8; j++) acc[i][j] = 0.f;

    const int lr = tid >> 2;          // 0..63
    const int lf = tid & 3;           // 0..3: float4 within BK=16

    for (int k0 = 0; k0 < K; k0 += 16) {
#pragma unroll
        for (int rr = 0; rr < 2; rr++) {
            int r = lr + rr*64;
            float4 va = *(const float4*)&A [(size_t)(m0+r)*K + k0 + lf*4];
            As[lf*4+0][r]=va.x; As[lf*4+1][r]=va.y; As[lf*4+2][r]=va.z; As[lf*4+3][r]=va.w;
            float4 vb = *(const float4*)&Bw[(size_t)(n0+r)*K + k0 + lf*4];
            Bs[lf*4+0][r]=vb.x; Bs[lf*4+1][r]=vb.y; Bs[lf*4+2][r]=vb.z; Bs[lf*4+3][r]=vb.w;
        }
        __syncthreads();
#pragma unroll
        for (int k = 0; k < 16; k++) {
            float a[8], b[8];
            *(float4*)&a[0] = *(const float4*)&As[k][ty*8];
            *(float4*)&a[4] = *(const float4*)&As[k][ty*8+4];
            *(float4*)&b[0] = *(const float4*)&Bs[k][tx*8];
            *(float4*)&b[4] = *(const float4*)&Bs[k][tx*8+4];
#pragma unroll
            for (int i = 0; i < 8; i++)
#pragma unroll
                for (int j = 0; j < 8; j++)
                    acc[i][j] = fmaf(a[i], b[j], acc[i][j]);
        }
        __syncthreads();
    }

    float pa = 0.f;
    if (prelu) pa = *prelu;
#pragma unroll
    for (int i = 0; i < 8; i++) {
        int row = m0 + ty*8 + i;
#pragma unroll
        for (int jc = 0; jc < 2; jc++) {
            float4 o; float* op = (float*)&o;
#pragma unroll
            for (int j = 0; j < 4; j++) {
                int col = n0 + tx*8 + jc*4 + j;
                float v = acc[i][jc*4+j];
                if (bias)  v += bias[col];
                if (prelu) v = (v >= 0.f) ? v : pa * v;
                op[j] = v;
            }
            *(float4*)&C[(size_t)row*N + n0 + tx*8 + jc*4] = o;
        }
    }
}

// ---------------- Flash attention (fp32, online softmax) -------------------
#define FA_BM 128
#define FA_BN 64

struct FaSmem {
    float Qs[HD][FA_BM+4];     // [d][r], q pre-scaled
    float Ks[HD][FA_BN+4];     // [d][c]
    float Vs[FA_BN][HD+4];     // [k][d]
    float Ps[FA_BM][FA_BN+4];  // scores -> probabilities
    float m_s[FA_BM], l_s[FA_BM], al_s[FA_BM];
};

__global__ __launch_bounds__(256) void flash_attn(const float* __restrict__ qkv,
                                                  float* __restrict__ out)
{
    extern __shared__ float smem_raw[];
    FaSmem& S = *(FaSmem*)smem_raw;
    const int tid = threadIdx.x;
    const int tx = tid & 15;          // 16 -> 4 dims each
    const int ty = tid >> 4;          // 16 -> 8 rows each
    const int bh = blockIdx.y;
    const int b  = bh >> 4, h = bh & 15;
    const int q0 = blockIdx.x * FA_BM;
    const float scale = 0.125f;       // hd^-0.5

    // Q tile (scaled), stored [d][r]
    for (int idx = tid; idx < FA_BM*16; idx += 256) {
        int r = idx >> 4, f = idx & 15;
        float4 v = *(const float4*)&qkv[(size_t)(b*SEQ + q0 + r)*QKVN + h*HD + f*4];
        S.Qs[f*4+0][r] = v.x*scale; S.Qs[f*4+1][r] = v.y*scale;
        S.Qs[f*4+2][r] = v.z*scale; S.Qs[f*4+3][r] = v.w*scale;
    }
    if (tid < FA_BM) { S.m_s[tid] = -1e30f; S.l_s[tid] = 0.f; }

    float o[8][4];
#pragma unroll
    for (int i = 0; i < 8; i++)
#pragma unroll
        for (int j = 0; j < 4; j++) o[i][j] = 0.f;

    for (int kv0 = 0; kv0 < SEQ; kv0 += FA_BN) {
        __syncthreads();  // prev-iter Ps/Vs reads done; also orders Q/init
        // K (transposed) + V tiles
        for (int idx = tid; idx < FA_BN*16; idx += 256) {
            int c = idx >> 4, f = idx & 15;
            const float* base = &qkv[(size_t)(b*SEQ + kv0 + c)*QKVN + h*HD + f*4];
            float4 kv_ = *(const float4*)(base + DIM);
            S.Ks[f*4+0][c]=kv_.x; S.Ks[f*4+1][c]=kv_.y; S.Ks[f*4+2][c]=kv_.z; S.Ks[f*4+3][c]=kv_.w;
            float4 vv  = *(const float4*)(base + 2*DIM);
            *(float4*)&S.Vs[c][f*4] = vv;
        }
        __syncthreads();

        // S = Q K^T  (8x4 per thread)
        float s[8][4];
#pragma unroll
        for (int i = 0; i < 8; i++)
#pragma unroll
            for (int j = 0; j < 4; j++) s[i][j] = 0.f;
#pragma unroll 4
        for (int d = 0; d < HD; d++) {
            float a[8], bq[4];
            *(float4*)&a[0]  = *(const float4*)&S.Qs[d][ty*8];
            *(float4*)&a[4]  = *(const float4*)&S.Qs[d][ty*8+4];
            *(float4*)&bq[0] = *(const float4*)&S.Ks[d][tx*4];
#pragma unroll
            for (int i = 0; i < 8; i++)
#pragma unroll
                for (int j = 0; j < 4; j++)
                    s[i][j] = fmaf(a[i], bq[j], s[i][j]);
        }
#pragma unroll
        for (int i = 0; i < 8; i++)
            *(float4*)&S.Ps[ty*8+i][tx*4] = make_float4(s[i][0], s[i][1], s[i][2], s[i][3]);
        __syncthreads();

        // online softmax: 2 threads per row
        {
            int row = tid >> 1, g = tid & 1;
            float mloc = -1e30f;
            for (int c = g; c < FA_BN; c += 2) mloc = fmaxf(mloc, S.Ps[row][c]);
            mloc = fmaxf(mloc, __shfl_xor_sync(0xffffffffu, mloc, 1));
            float mold = S.m_s[row];
            float mnew = fmaxf(mold, mloc);
            float lsum = 0.f;
            for (int c = g; c < FA_BN; c += 2) {
                float p = __expf(S.Ps[row][c] - mnew);
                S.Ps[row][c] = p;
                lsum += p;
            }
            lsum += __shfl_xor_sync(0xffffffffu, lsum, 1);
            if (g == 0) {
                float al = __expf(mold - mnew);
                S.l_s[row] = al * S.l_s[row] + lsum;
                S.m_s[row] = mnew;
                S.al_s[row] = al;
            }
        }
        __syncthreads();

        // O = al*O + P @ V
        float al[8];
#pragma unroll
        for (int i = 0; i < 8; i++) al[i] = S.al_s[ty*8+i];
#pragma unroll
        for (int i = 0; i < 8; i++)
#pragma unroll
            for (int j = 0; j < 4; j++) o[i][j] *= al[i];
#pragma unroll 4
        for (int k = 0; k < FA_BN; k++) {
            float4 v4 = *(const float4*)&S.Vs[k][tx*4];
#pragma unroll
            for (int i = 0; i < 8; i++) {
                float p = S.Ps[ty*8+i][k];
                o[i][0] = fmaf(p, v4.x, o[i][0]);
                o[i][1] = fmaf(p, v4.y, o[i][1]);
                o[i][2] = fmaf(p, v4.z, o[i][2]);
                o[i][3] = fmaf(p, v4.w, o[i][3]);
            }
        }
    }
    __syncthreads();
#pragma unroll
    for (int i = 0; i < 8; i++) {
        int r = ty*8 + i;
        float inv = 1.f / S.l_s[r];
        float4 ov = make_float4(o[i][0]*inv, o[i][1]*inv, o[i][2]*inv, o[i][3]*inv);
        *(float4*)&out[(size_t)(b*SEQ + q0 + r)*DIM + h*HD + tx*4] = ov;
    }
}

// ---------------- residual add + LayerNorm (one block per row) -------------
__global__ __launch_bounds__(256) void add_ln(
    const float* __restrict__ a, const float* __restrict__ bres,
    const float* __restrict__ g, const float* __restrict__ beta,
    float* __restrict__ out)
{
    const int row = blockIdx.x;
    const int tid = threadIdx.x;
    float4 av = *(const float4*)&a   [(size_t)row*DIM + tid*4];
    float4 bv = *(const float4*)&bres[(size_t)row*DIM + tid*4];
    float v[4] = {av.x+bv.x, av.y+bv.y, av.z+bv.z, av.w+bv.w};
    float s  = v[0]+v[1]+v[2]+v[3];
    float sq = v[0]*v[0]+v[1]*v[1]+v[2]*v[2]+v[3]*v[3];

    __shared__ float rs[256], rq[256];
    rs[tid] = s; rq[tid] = sq;
    __syncthreads();
    for (int off = 128; off > 0; off >>= 1) {
        if (tid < off) { rs[tid] += rs[tid+off]; rq[tid] += rq[tid+off]; }
        __syncthreads();
    }
    float mean = rs[0] * (1.f/DIM);
    float var  = rq[0] * (1.f/DIM) - mean*mean;
    float rstd = rsqrtf(var + 1e-5f);

    float4 gv = *(const float4*)&g[tid*4];
    float4 ev = *(const float4*)&beta[tid*4];
    float4 ov;
    ov.x = (v[0]-mean)*rstd*gv.x + ev.x;
    ov.y = (v[1]-mean)*rstd*gv.y + ev.y;
    ov.z = (v[2]-mean)*rstd*gv.z + ev.z;
    ov.w = (v[3]-mean)*rstd*gv.w + ev.w;
    *(float4*)&out[(size_t)row*DIM + tid*4] = ov;
}

// ---------------- launch ---------------------------------------------------
extern "C" void kernel_launch(void* const* d_in, const int* in_sizes, int n_in,
                              void* d_out, int out_size)
{
    (void)in_sizes; (void)n_in; (void)out_size;
    const float* x       = (const float*)d_in[0];
    const float* qkv_w   = (const float*)d_in[1];
    const float* proj_w  = (const float*)d_in[2];
    const float* proj_b  = (const float*)d_in[3];
    const float* ln1_g   = (const float*)d_in[4];
    const float* ln1_b   = (const float*)d_in[5];
    const float* w1      = (const float*)d_in[6];
    const float* b1      = (const float*)d_in[7];
    const float* prelu_a = (const float*)d_in[8];
    const float* w2      = (const float*)d_in[9];
    const float* b2      = (const float*)d_in[10];
    const float* ln2_g   = (const float*)d_in[11];
    const float* ln2_b   = (const float*)d_in[12];
    float* out = (float*)d_out;

    float *qkv, *attn, *x1, *tmp, *hbuf;
    cudaGetSymbolAddress((void**)&qkv,  g_qkv);
    cudaGetSymbolAddress((void**)&attn, g_attn);
    cudaGetSymbolAddress((void**)&x1,   g_x1);
    cudaGetSymbolAddress((void**)&tmp,  g_tmp);
    cudaGetSymbolAddress((void**)&hbuf, g_h);

    const dim3 blk(256);
    const int fasz = (int)sizeof(FaSmem);
    cudaFuncSetAttribute(flash_attn, cudaFuncAttributeMaxDynamicSharedMemorySize, fasz);

    // 1) qkv = x @ qkv_w^T
    sgemm_nt<<<dim3(QKVN/128, MROWS/128), blk>>>(x, qkv_w, nullptr, nullptr,
                                                 qkv, MROWS, QKVN, DIM);
    // 2) attention
    flash_attn<<<dim3(SEQ/FA_BM, B_SZ*HEADS), blk, fasz>>>(qkv, attn);
    // 3) proj
    sgemm_nt<<<dim3(DIM/128, MROWS/128), blk>>>(attn, proj_w, proj_b, nullptr,
                                                tmp, MROWS, DIM, DIM);
    // 4) x1 = LN(x + proj)
    add_ln<<<MROWS, blk>>>(x, tmp, ln1_g, ln1_b, x1);
    // 5) h = PReLU(x1 @ w1^T + b1)
    sgemm_nt<<<dim3(HID/128, MROWS/128), blk>>>(x1, w1, b1, prelu_a,
                                                hbuf, MROWS, HID, DIM);
    // 6) h2 = h @ w2^T + b2
    sgemm_nt<<<dim3(DIM/128, MROWS/128), blk>>>(hbuf, w2, b2, nullptr,
                                                tmp, MROWS, DIM, HID);
    // 7) out = LN(x1 + h2)
    add_ln<<<MROWS, blk>>>(x1, tmp, ln2_g, ln2_b, out);
}

// round 4
// speedup vs baseline: 1.6920x; 1.6920x over previous
#include <cuda_runtime.h>
#include <cuda_bf16.h>
#include <cstdint>
#include <math.h>

#define B_SZ 4
#define SEQ  2048
#define DIM  1024
#define HEADS 16
#define HD   64
#define HID  4096
#define MROWS (B_SZ*SEQ)   /* 8192 */
#define QKVN  (3*DIM)      /* 3072 */

typedef __nv_bfloat16 bf16;

// ---------------- scratch (static device globals; no runtime alloc) --------
__device__ float g_qkv [(size_t)MROWS*QKVN];
__device__ float g_x1  [(size_t)MROWS*DIM];
__device__ float g_tmp [(size_t)MROWS*DIM];
__device__ bf16  g_xh  [(size_t)MROWS*DIM];
__device__ bf16  g_xl  [(size_t)MROWS*DIM];
__device__ bf16  g_ah  [(size_t)MROWS*DIM];
__device__ bf16  g_al  [(size_t)MROWS*DIM];
__device__ bf16  g_x1h [(size_t)MROWS*DIM];
__device__ bf16  g_x1l [(size_t)MROWS*DIM];
__device__ bf16  g_hh  [(size_t)MROWS*HID];
__device__ bf16  g_hl  [(size_t)MROWS*HID];
__device__ bf16  g_wqh [(size_t)QKVN*DIM];
__device__ bf16  g_wql [(size_t)QKVN*DIM];
__device__ bf16  g_wph [(size_t)DIM*DIM];
__device__ bf16  g_wpl [(size_t)DIM*DIM];
__device__ bf16  g_w1h [(size_t)HID*DIM];
__device__ bf16  g_w1l [(size_t)HID*DIM];
__device__ bf16  g_w2h [(size_t)DIM*HID];
__device__ bf16  g_w2l [(size_t)DIM*HID];

// ---------------- helpers ---------------------------------------------------
__device__ __forceinline__ uint32_t smem_u32(const void* p) {
    uint32_t a;
    asm("{ .reg .u64 t; cvta.to.shared.u64 t, %1; cvt.u32.u64 %0, t; }" : "=r"(a) : "l"(p));
    return a;
}
__device__ __forceinline__ void ldsm_x4(uint32_t& r0, uint32_t& r1, uint32_t& r2,
                                        uint32_t& r3, uint32_t addr) {
    asm volatile("ldmatrix.sync.aligned.m8n8.x4.shared.b16 {%0,%1,%2,%3}, [%4];"
                 : "=r"(r0), "=r"(r1), "=r"(r2), "=r"(r3) : "r"(addr));
}
__device__ __forceinline__ void mma_bf16(float* c, const uint32_t* a, const uint32_t* b) {
    asm volatile("mma.sync.aligned.m16n8k16.row.col.f32.bf16.bf16.f32 "
                 "{%0,%1,%2,%3}, {%4,%5,%6,%7}, {%8,%9}, {%0,%1,%2,%3};"
                 : "+f"(c[0]), "+f"(c[1]), "+f"(c[2]), "+f"(c[3])
                 : "r"(a[0]), "r"(a[1]), "r"(a[2]), "r"(a[3]), "r"(b[0]), "r"(b[1]));
}
__device__ __forceinline__ void split2(float v, bf16& h, bf16& l) {
    h = __float2bfloat16(v);
    l = __float2bfloat16(v - __bfloat162float(h));
}

// ---------------- fp32 -> bf16 hi/lo split ----------------------------------
__global__ __launch_bounds__(256) void split_bf16(
    const float* __restrict__ src, bf16* __restrict__ hi, bf16* __restrict__ lo)
{
    size_t i = ((size_t)blockIdx.x * 256 + threadIdx.x) * 4;
    float4 v = *(const float4*)&src[i];
    bf16 h0,l0,h1,l1,h2,l2,h3,l3;
    split2(v.x,h0,l0); split2(v.y,h1,l1); split2(v.z,h2,l2); split2(v.w,h3,l3);
    __nv_bfloat162 ha; ha.x=h0; ha.y=h1;
    __nv_bfloat162 hb; hb.x=h2; hb.y=h3;
    __nv_bfloat162 la; la.x=l0; la.y=l1;
    __nv_bfloat162 lb; lb.x=l2; lb.y=l3;
    *(__nv_bfloat162*)&hi[i]   = ha; *(__nv_bfloat162*)&hi[i+2] = hb;
    *(__nv_bfloat162*)&lo[i]   = la; *(__nv_bfloat162*)&lo[i+2] = lb;
}

// ---------------- split-bf16 GEMM on mma.sync (HMMA) ------------------------
// C[M,N] = (Ah+Al)[M,K] @ (Bh+Bl)[N,K]^T  (lo*lo dropped), fp32 reg accum.
// CTA 128x128, BK=32, 8 warps (2 m x 4 n), warp tile 64x32, m16n8k16.
#define BK   32
#define APAD 8
#define LDS_W (BK + APAD)   /* 40 bf16 = 80B row stride */

__global__ __launch_bounds__(256) void gemm_mma(
    const bf16* __restrict__ Ah, const bf16* __restrict__ Al,
    const bf16* __restrict__ Bh, const bf16* __restrict__ Bl,
    const float* __restrict__ bias, const float* __restrict__ prelu,
    float* __restrict__ Cf, bf16* __restrict__ Ch, bf16* __restrict__ Cl,
    int M, int N, int K)
{
    __shared__ bf16 Ah_s[128][LDS_W], Al_s[128][LDS_W];
    __shared__ bf16 Bh_s[128][LDS_W], Bl_s[128][LDS_W];

    const int tid  = threadIdx.x;
    const int lane = tid & 31;
    const int wid  = tid >> 5;
    const int wm   = wid & 1;        // 2 warps in m
    const int wn   = wid >> 1;       // 4 warps in n
    const int m0   = blockIdx.y * 128;
    const int n0   = blockIdx.x * 128;

    float acc[4][4][4];
#pragma unroll
    for (int i = 0; i < 4; i++)
#pragma unroll
        for (int j = 0; j < 4; j++)
#pragma unroll
            for (int r = 0; r < 4; r++) acc[i][j][r] = 0.f;

    // ldmatrix lane addressing
    const int mat = lane >> 3, rin = lane & 7;
    // A frag (m16k16): row = mbase + (mat&1)*8 + rin, col = kk + (mat>>1)*8
    const int a_row_off = (mat & 1) * 8 + rin;
    const int a_col_off = (mat >> 1) * 8;
    // B frag pair (n16k16): row = nbase + (mat>>1)*8 + rin, col = kk + (mat&1)*8
    const int b_row_off = (mat >> 1) * 8 + rin;
    const int b_col_off = (mat & 1) * 8;

    for (int k0 = 0; k0 < K; k0 += BK) {
        // load chunk: each array 128x32 bf16, 512 float4 per array
#pragma unroll
        for (int v = 0; v < 2; v++) {
            int idx = tid + v * 256;
            int r = idx >> 2, c8 = (idx & 3) * 8;
            size_t goA = (size_t)(m0 + r) * K + k0 + c8;
            size_t goB = (size_t)(n0 + r) * K + k0 + c8;
            *(float4*)&Ah_s[r][c8] = *(const float4*)&Ah[goA];
            *(float4*)&Al_s[r][c8] = *(const float4*)&Al[goA];
            *(float4*)&Bh_s[r][c8] = *(const float4*)&Bh[goB];
            *(float4*)&Bl_s[r][c8] = *(const float4*)&Bl[goB];
        }
        __syncthreads();

#pragma unroll
        for (int kk = 0; kk < BK; kk += 16) {
            uint32_t ah[4][4], al[4][4], bh[4][2], bl[4][2];
#pragma unroll
            for (int mi = 0; mi < 4; mi++) {
                int row = wm * 64 + mi * 16 + a_row_off;
                uint32_t ad = smem_u32(&Ah_s[row][kk + a_col_off]);
                ldsm_x4(ah[mi][0], ah[mi][1], ah[mi][2], ah[mi][3], ad);
                uint32_t ad2 = smem_u32(&Al_s[row][kk + a_col_off]);
                ldsm_x4(al[mi][0], al[mi][1], al[mi][2], al[mi][3], ad2);
            }
#pragma unroll
            for (int ng = 0; ng < 2; ng++) {
                int row = wn * 32 + ng * 16 + b_row_off;
                uint32_t bd = smem_u32(&Bh_s[row][kk + b_col_off]);
                ldsm_x4(bh[ng*2][0], bh[ng*2][1], bh[ng*2+1][0], bh[ng*2+1][1], bd);
                uint32_t bd2 = smem_u32(&Bl_s[row][kk + b_col_off]);
                ldsm_x4(bl[ng*2][0], bl[ng*2][1], bl[ng*2+1][0], bl[ng*2+1][1], bd2);
            }
#pragma unroll
            for (int mi = 0; mi < 4; mi++)
#pragma unroll
                for (int ni = 0; ni < 4; ni++) {
                    mma_bf16(acc[mi][ni], ah[mi], bh[ni]);
                    mma_bf16(acc[mi][ni], ah[mi], bl[ni]);
                    mma_bf16(acc[mi][ni], al[mi], bh[ni]);
                }
        }
        __syncthreads();
    }

    // epilogue
    const float pa = prelu ? *prelu : 0.f;
#pragma unroll
    for (int mi = 0; mi < 4; mi++) {
#pragma unroll
        for (int ni = 0; ni < 4; ni++) {
            int row0 = m0 + wm * 64 + mi * 16 + (lane >> 2);
            int col  = n0 + wn * 32 + ni * 8 + (lane & 3) * 2;
#pragma unroll
            for (int half = 0; half < 2; half++) {
                int row = row0 + half * 8;
                float v0 = acc[mi][ni][half * 2 + 0];
                float v1 = acc[mi][ni][half * 2 + 1];
                if (bias) { v0 += bias[col]; v1 += bias[col + 1]; }
                if (prelu) {
                    v0 = (v0 >= 0.f) ? v0 : pa * v0;
                    v1 = (v1 >= 0.f) ? v1 : pa * v1;
                }
                size_t o = (size_t)row * N + col;
                if (Cf) *(float2*)&Cf[o] = make_float2(v0, v1);
                if (Ch) {
                    bf16 h0,l0,h1,l1;
                    split2(v0, h0, l0); split2(v1, h1, l1);
                    __nv_bfloat162 hh2; hh2.x = h0; hh2.y = h1;
                    __nv_bfloat162 ll2; ll2.x = l0; ll2.y = l1;
                    *(__nv_bfloat162*)&Ch[o] = hh2;
                    *(__nv_bfloat162*)&Cl[o] = ll2;
                }
            }
        }
    }
}

// ---------------- Flash attention (fp32, online softmax) -------------------
#define FA_BM 128
#define FA_BN 64

struct FaSmem {
    float Qs[HD][FA_BM+4];
    float Ks[HD][FA_BN+4];
    float Vs[FA_BN][HD+4];
    float Ps[FA_BM][FA_BN+4];
    float m_s[FA_BM], l_s[FA_BM], al_s[FA_BM];
};

__global__ __launch_bounds__(256) void flash_attn(const float* __restrict__ qkv,
                                                  bf16* __restrict__ out_h,
                                                  bf16* __restrict__ out_l)
{
    extern __shared__ float smem_raw[];
    FaSmem& S = *(FaSmem*)smem_raw;
    const int tid = threadIdx.x;
    const int tx = tid & 15;
    const int ty = tid >> 4;
    const int bh = blockIdx.y;
    const int b  = bh >> 4, h = bh & 15;
    const int q0 = blockIdx.x * FA_BM;
    const float scale = 0.125f;

    for (int idx = tid; idx < FA_BM*16; idx += 256) {
        int r = idx >> 4, f = idx & 15;
        float4 v = *(const float4*)&qkv[(size_t)(b*SEQ + q0 + r)*QKVN + h*HD + f*4];
        S.Qs[f*4+0][r] = v.x*scale; S.Qs[f*4+1][r] = v.y*scale;
        S.Qs[f*4+2][r] = v.z*scale; S.Qs[f*4+3][r] = v.w*scale;
    }
    if (tid < FA_BM) { S.m_s[tid] = -1e30f; S.l_s[tid] = 0.f; }

    float o[8][4];
#pragma unroll
    for (int i = 0; i < 8; i++)
#pragma unroll
        for (int j = 0; j < 4; j++) o[i][j] = 0.f;

    for (int kv0 = 0; kv0 < SEQ; kv0 += FA_BN) {
        __syncthreads();
        for (int idx = tid; idx < FA_BN*16; idx += 256) {
            int c = idx >> 4, f = idx & 15;
            const float* base = &qkv[(size_t)(b*SEQ + kv0 + c)*QKVN + h*HD + f*4];
            float4 kv_ = *(const float4*)(base + DIM);
            S.Ks[f*4+0][c]=kv_.x; S.Ks[f*4+1][c]=kv_.y; S.Ks[f*4+2][c]=kv_.z; S.Ks[f*4+3][c]=kv_.w;
            float4 vv  = *(const float4*)(base + 2*DIM);
            *(float4*)&S.Vs[c][f*4] = vv;
        }
        __syncthreads();

        float s[8][4];
#pragma unroll
        for (int i = 0; i < 8; i++)
#pragma unroll
            for (int j = 0; j < 4; j++) s[i][j] = 0.f;
#pragma unroll 4
        for (int d = 0; d < HD; d++) {
            float a[8], bq[4];
            *(float4*)&a[0]  = *(const float4*)&S.Qs[d][ty*8];
            *(float4*)&a[4]  = *(const float4*)&S.Qs[d][ty*8+4];
            *(float4*)&bq[0] = *(const float4*)&S.Ks[d][tx*4];
#pragma unroll
            for (int i = 0; i < 8; i++)
#pragma unroll
                for (int j = 0; j < 4; j++)
                    s[i][j] = fmaf(a[i], bq[j], s[i][j]);
        }
#pragma unroll
        for (int i = 0; i < 8; i++)
            *(float4*)&S.Ps[ty*8+i][tx*4] = make_float4(s[i][0], s[i][1], s[i][2], s[i][3]);
        __syncthreads();

        {
            int row = tid >> 1, g = tid & 1;
            float mloc = -1e30f;
            for (int c = g; c < FA_BN; c += 2) mloc = fmaxf(mloc, S.Ps[row][c]);
            mloc = fmaxf(mloc, __shfl_xor_sync(0xffffffffu, mloc, 1));
            float mold = S.m_s[row];
            float mnew = fmaxf(mold, mloc);
            float lsum = 0.f;
            for (int c = g; c < FA_BN; c += 2) {
                float p = __expf(S.Ps[row][c] - mnew);
                S.Ps[row][c] = p;
                lsum += p;
            }
            lsum += __shfl_xor_sync(0xffffffffu, lsum, 1);
            if (g == 0) {
                float al = __expf(mold - mnew);
                S.l_s[row] = al * S.l_s[row] + lsum;
                S.m_s[row] = mnew;
                S.al_s[row] = al;
            }
        }
        __syncthreads();

        float al[8];
#pragma unroll
        for (int i = 0; i < 8; i++) al[i] = S.al_s[ty*8+i];
#pragma unroll
        for (int i = 0; i < 8; i++)
#pragma unroll
            for (int j = 0; j < 4; j++) o[i][j] *= al[i];
#pragma unroll 4
        for (int k = 0; k < FA_BN; k++) {
            float4 v4 = *(const float4*)&S.Vs[k][tx*4];
#pragma unroll
            for (int i = 0; i < 8; i++) {
                float p = S.Ps[ty*8+i][k];
                o[i][0] = fmaf(p, v4.x, o[i][0]);
                o[i][1] = fmaf(p, v4.y, o[i][1]);
                o[i][2] = fmaf(p, v4.z, o[i][2]);
                o[i][3] = fmaf(p, v4.w, o[i][3]);
            }
        }
    }
    __syncthreads();
#pragma unroll
    for (int i = 0; i < 8; i++) {
        int r = ty*8 + i;
        float inv = 1.f / S.l_s[r];
        float vv[4] = {o[i][0]*inv, o[i][1]*inv, o[i][2]*inv, o[i][3]*inv};
        bf16 h0,l0,h1,l1,h2,l2,h3,l3;
        split2(vv[0],h0,l0); split2(vv[1],h1,l1); split2(vv[2],h2,l2); split2(vv[3],h3,l3);
        __nv_bfloat162 ha; ha.x=h0; ha.y=h1;
        __nv_bfloat162 hb; hb.x=h2; hb.y=h3;
        __nv_bfloat162 la; la.x=l0; la.y=l1;
        __nv_bfloat162 lb; lb.x=l2; lb.y=l3;
        size_t base = (size_t)(b*SEQ + q0 + r)*DIM + h*HD + tx*4;
        *(__nv_bfloat162*)&out_h[base]   = ha;
        *(__nv_bfloat162*)&out_h[base+2] = hb;
        *(__nv_bfloat162*)&out_l[base]   = la;
        *(__nv_bfloat162*)&out_l[base+2] = lb;
    }
}

// ---------------- residual add + LayerNorm ---------------------------------
__global__ __launch_bounds__(256) void add_ln(
    const float* __restrict__ a, const float* __restrict__ bres,
    const float* __restrict__ g, const float* __restrict__ beta,
    float* __restrict__ out, bf16* __restrict__ out_h, bf16* __restrict__ out_l)
{
    const int row = blockIdx.x;
    const int tid = threadIdx.x;
    float4 av = *(const float4*)&a   [(size_t)row*DIM + tid*4];
    float4 bv = *(const float4*)&bres[(size_t)row*DIM + tid*4];
    float v[4] = {av.x+bv.x, av.y+bv.y, av.z+bv.z, av.w+bv.w};
    float s  = v[0]+v[1]+v[2]+v[3];
    float sq = v[0]*v[0]+v[1]*v[1]+v[2]*v[2]+v[3]*v[3];

    __shared__ float rs[256], rq[256];
    rs[tid] = s; rq[tid] = sq;
    __syncthreads();
    for (int off = 128; off > 0; off >>= 1) {
        if (tid < off) { rs[tid] += rs[tid+off]; rq[tid] += rq[tid+off]; }
        __syncthreads();
    }
    float mean = rs[0] * (1.f/DIM);
    float var  = rq[0] * (1.f/DIM) - mean*mean;
    float rstd = rsqrtf(var + 1e-5f);

    float4 gv = *(const float4*)&g[tid*4];
    float4 ev = *(const float4*)&beta[tid*4];
    float ov[4];
    ov[0] = (v[0]-mean)*rstd*gv.x + ev.x;
    ov[1] = (v[1]-mean)*rstd*gv.y + ev.y;
    ov[2] = (v[2]-mean)*rstd*gv.z + ev.z;
    ov[3] = (v[3]-mean)*rstd*gv.w + ev.w;
    *(float4*)&out[(size_t)row*DIM + tid*4] = make_float4(ov[0],ov[1],ov[2],ov[3]);
    if (out_h) {
        bf16 h0,l0,h1,l1,h2,l2,h3,l3;
        split2(ov[0],h0,l0); split2(ov[1],h1,l1); split2(ov[2],h2,l2); split2(ov[3],h3,l3);
        __nv_bfloat162 ha; ha.x=h0; ha.y=h1;
        __nv_bfloat162 hb; hb.x=h2; hb.y=h3;
        __nv_bfloat162 la; la.x=l0; la.y=l1;
        __nv_bfloat162 lb; lb.x=l2; lb.y=l3;
        size_t base = (size_t)row*DIM + tid*4;
        *(__nv_bfloat162*)&out_h[base]   = ha;
        *(__nv_bfloat162*)&out_h[base+2] = hb;
        *(__nv_bfloat162*)&out_l[base]   = la;
        *(__nv_bfloat162*)&out_l[base+2] = lb;
    }
}

// ---------------- launch ---------------------------------------------------
extern "C" void kernel_launch(void* const* d_in, const int* in_sizes, int n_in,
                              void* d_out, int out_size)
{
    (void)in_sizes; (void)n_in; (void)out_size;
    const float* x       = (const float*)d_in[0];
    const float* qkv_w   = (const float*)d_in[1];
    const float* proj_w  = (const float*)d_in[2];
    const float* proj_b  = (const float*)d_in[3];
    const float* ln1_g   = (const float*)d_in[4];
    const float* ln1_b   = (const float*)d_in[5];
    const float* w1      = (const float*)d_in[6];
    const float* b1      = (const float*)d_in[7];
    const float* prelu_a = (const float*)d_in[8];
    const float* w2      = (const float*)d_in[9];
    const float* b2      = (const float*)d_in[10];
    const float* ln2_g   = (const float*)d_in[11];
    const float* ln2_b   = (const float*)d_in[12];
    float* out = (float*)d_out;

    float *qkv, *x1, *tmp;
    bf16 *xh,*xl,*ah,*al,*x1h,*x1l,*hh,*hl,*wqh,*wql,*wph,*wpl,*w1h,*w1l,*w2h,*w2l;
    cudaGetSymbolAddress((void**)&qkv, g_qkv);
    cudaGetSymbolAddress((void**)&x1,  g_x1);
    cudaGetSymbolAddress((void**)&tmp, g_tmp);
    cudaGetSymbolAddress((void**)&xh,  g_xh);  cudaGetSymbolAddress((void**)&xl,  g_xl);
    cudaGetSymbolAddress((void**)&ah,  g_ah);  cudaGetSymbolAddress((void**)&al,  g_al);
    cudaGetSymbolAddress((void**)&x1h, g_x1h); cudaGetSymbolAddress((void**)&x1l, g_x1l);
    cudaGetSymbolAddress((void**)&hh,  g_hh);  cudaGetSymbolAddress((void**)&hl,  g_hl);
    cudaGetSymbolAddress((void**)&wqh, g_wqh); cudaGetSymbolAddress((void**)&wql, g_wql);
    cudaGetSymbolAddress((void**)&wph, g_wph); cudaGetSymbolAddress((void**)&wpl, g_wpl);
    cudaGetSymbolAddress((void**)&w1h, g_w1h); cudaGetSymbolAddress((void**)&w1l, g_w1l);
    cudaGetSymbolAddress((void**)&w2h, g_w2h); cudaGetSymbolAddress((void**)&w2l, g_w2l);

    const dim3 blk(256);
    const int fasz = (int)sizeof(FaSmem);
    cudaFuncSetAttribute(flash_attn, cudaFuncAttributeMaxDynamicSharedMemorySize, fasz);

    // splits (inputs + weights)
    split_bf16<<<(MROWS*DIM)/1024, blk>>>(x, xh, xl);
    split_bf16<<<(QKVN*DIM)/1024, blk>>>(qkv_w, wqh, wql);
    split_bf16<<<(DIM*DIM)/1024,  blk>>>(proj_w, wph, wpl);
    split_bf16<<<(HID*DIM)/1024,  blk>>>(w1, w1h, w1l);
    split_bf16<<<(DIM*HID)/1024,  blk>>>(w2, w2h, w2l);

    // 1) qkv = x @ qkv_w^T (fp32 out for attention)
    gemm_mma<<<dim3(QKVN/128, MROWS/128), blk>>>(
        xh, xl, wqh, wql, nullptr, nullptr, qkv, nullptr, nullptr, MROWS, QKVN, DIM);
    // 2) attention -> bf16 hi/lo
    flash_attn<<<dim3(SEQ/FA_BM, B_SZ*HEADS), blk, fasz>>>(qkv, ah, al);
    // 3) proj -> tmp fp32
    gemm_mma<<<dim3(DIM/128, MROWS/128), blk>>>(
        ah, al, wph, wpl, proj_b, nullptr, tmp, nullptr, nullptr, MROWS, DIM, DIM);
    // 4) x1 = LN(x + proj), also split
    add_ln<<<MROWS, blk>>>(x, tmp, ln1_g, ln1_b, x1, x1h, x1l);
    // 5) h = PReLU(x1 @ w1^T + b1) -> bf16 hi/lo only
    gemm_mma<<<dim3(HID/128, MROWS/128), blk>>>(
        x1h, x1l, w1h, w1l, b1, prelu_a, nullptr, hh, hl, MROWS, HID, DIM);
    // 6) h2 = h @ w2^T + b2 -> tmp fp32
    gemm_mma<<<dim3(DIM/128, MROWS/128), blk>>>(
        hh, hl, w2h, w2l, b2, nullptr, tmp, nullptr, nullptr, MROWS, DIM, HID);
    // 7) out = LN(x1 + h2)
    add_ln<<<MROWS, blk>>>(x1, tmp, ln2_g, ln2_b, out, nullptr, nullptr);
}

// round 5
// speedup vs baseline: 2.0424x; 1.2071x over previous
#include <cuda_runtime.h>
#include <cuda_bf16.h>
#include <cstdint>
#include <math.h>

#define B_SZ 4
#define SEQ  2048
#define DIM  1024
#define HEADS 16
#define HD   64
#define HID  4096
#define MROWS (B_SZ*SEQ)   /* 8192 */
#define QKVN  (3*DIM)      /* 3072 */

typedef __nv_bfloat16 bf16;

// ---------------- scratch (static device globals; no runtime alloc) --------
__device__ float g_qkv [(size_t)MROWS*QKVN];
__device__ float g_x1  [(size_t)MROWS*DIM];
__device__ float g_tmp [(size_t)MROWS*DIM];
__device__ bf16  g_xh  [(size_t)MROWS*DIM];
__device__ bf16  g_xl  [(size_t)MROWS*DIM];
__device__ bf16  g_ah  [(size_t)MROWS*DIM];
__device__ bf16  g_al  [(size_t)MROWS*DIM];
__device__ bf16  g_x1h [(size_t)MROWS*DIM];
__device__ bf16  g_x1l [(size_t)MROWS*DIM];
__device__ bf16  g_hh  [(size_t)MROWS*HID];
__device__ bf16  g_hl  [(size_t)MROWS*HID];
__device__ bf16  g_wqh [(size_t)QKVN*DIM];
__device__ bf16  g_wql [(size_t)QKVN*DIM];
__device__ bf16  g_wph [(size_t)DIM*DIM];
__device__ bf16  g_wpl [(size_t)DIM*DIM];
__device__ bf16  g_w1h [(size_t)HID*DIM];
__device__ bf16  g_w1l [(size_t)HID*DIM];
__device__ bf16  g_w2h [(size_t)DIM*HID];
__device__ bf16  g_w2l [(size_t)DIM*HID];

// ---------------- helpers ---------------------------------------------------
__device__ __forceinline__ uint32_t smem_u32(const void* p) {
    uint32_t a;
    asm("{ .reg .u64 t; cvta.to.shared.u64 t, %1; cvt.u32.u64 %0, t; }" : "=r"(a) : "l"(p));
    return a;
}
__device__ __forceinline__ void ldsm_x4(uint32_t& r0, uint32_t& r1, uint32_t& r2,
                                        uint32_t& r3, uint32_t addr) {
    asm volatile("ldmatrix.sync.aligned.m8n8.x4.shared.b16 {%0,%1,%2,%3}, [%4];"
                 : "=r"(r0), "=r"(r1), "=r"(r2), "=r"(r3) : "r"(addr));
}
__device__ __forceinline__ void mma_bf16(float* c, const uint32_t* a, const uint32_t* b) {
    asm volatile("mma.sync.aligned.m16n8k16.row.col.f32.bf16.bf16.f32 "
                 "{%0,%1,%2,%3}, {%4,%5,%6,%7}, {%8,%9}, {%0,%1,%2,%3};"
                 : "+f"(c[0]), "+f"(c[1]), "+f"(c[2]), "+f"(c[3])
                 : "r"(a[0]), "r"(a[1]), "r"(a[2]), "r"(a[3]), "r"(b[0]), "r"(b[1]));
}
__device__ __forceinline__ void split2(float v, bf16& h, bf16& l) {
    h = __float2bfloat16(v);
    l = __float2bfloat16(v - __bfloat162float(h));
}
__device__ __forceinline__ void pack2(float a, float b, uint32_t& h, uint32_t& l) {
    bf16 ha = __float2bfloat16(a), hb = __float2bfloat16(b);
    bf16 la = __float2bfloat16(a - __bfloat162float(ha));
    bf16 lb = __float2bfloat16(b - __bfloat162float(hb));
    __nv_bfloat162 H; H.x = ha; H.y = hb;
    __nv_bfloat162 L; L.x = la; L.y = lb;
    h = *(uint32_t*)&H; l = *(uint32_t*)&L;
}

// ---------------- fp32 -> bf16 hi/lo split ----------------------------------
__global__ __launch_bounds__(256) void split_bf16(
    const float* __restrict__ src, bf16* __restrict__ hi, bf16* __restrict__ lo)
{
    size_t i = ((size_t)blockIdx.x * 256 + threadIdx.x) * 4;
    float4 v = *(const float4*)&src[i];
    bf16 h0,l0,h1,l1,h2,l2,h3,l3;
    split2(v.x,h0,l0); split2(v.y,h1,l1); split2(v.z,h2,l2); split2(v.w,h3,l3);
    __nv_bfloat162 ha; ha.x=h0; ha.y=h1;
    __nv_bfloat162 hb; hb.x=h2; hb.y=h3;
    __nv_bfloat162 la; la.x=l0; la.y=l1;
    __nv_bfloat162 lb; lb.x=l2; lb.y=l3;
    *(__nv_bfloat162*)&hi[i]   = ha; *(__nv_bfloat162*)&hi[i+2] = hb;
    *(__nv_bfloat162*)&lo[i]   = la; *(__nv_bfloat162*)&lo[i+2] = lb;
}

// ---------------- split-bf16 GEMM on mma.sync (HMMA) ------------------------
#define BK   32
#define APAD 8
#define LDS_W (BK + APAD)

__global__ __launch_bounds__(256) void gemm_mma(
    const bf16* __restrict__ Ah, const bf16* __restrict__ Al,
    const bf16* __restrict__ Bh, const bf16* __restrict__ Bl,
    const float* __restrict__ bias, const float* __restrict__ prelu,
    float* __restrict__ Cf, bf16* __restrict__ Ch, bf16* __restrict__ Cl,
    int M, int N, int K)
{
    __shared__ bf16 Ah_s[128][LDS_W], Al_s[128][LDS_W];
    __shared__ bf16 Bh_s[128][LDS_W], Bl_s[128][LDS_W];

    const int tid  = threadIdx.x;
    const int lane = tid & 31;
    const int wid  = tid >> 5;
    const int wm   = wid & 1;
    const int wn   = wid >> 1;
    const int m0   = blockIdx.y * 128;
    const int n0   = blockIdx.x * 128;

    float acc[4][4][4];
#pragma unroll
    for (int i = 0; i < 4; i++)
#pragma unroll
        for (int j = 0; j < 4; j++)
#pragma unroll
            for (int r = 0; r < 4; r++) acc[i][j][r] = 0.f;

    const int mat = lane >> 3, rin = lane & 7;
    const int a_row_off = (mat & 1) * 8 + rin;
    const int a_col_off = (mat >> 1) * 8;
    const int b_row_off = (mat >> 1) * 8 + rin;
    const int b_col_off = (mat & 1) * 8;

    for (int k0 = 0; k0 < K; k0 += BK) {
#pragma unroll
        for (int v = 0; v < 2; v++) {
            int idx = tid + v * 256;
            int r = idx >> 2, c8 = (idx & 3) * 8;
            size_t goA = (size_t)(m0 + r) * K + k0 + c8;
            size_t goB = (size_t)(n0 + r) * K + k0 + c8;
            *(float4*)&Ah_s[r][c8] = *(const float4*)&Ah[goA];
            *(float4*)&Al_s[r][c8] = *(const float4*)&Al[goA];
            *(float4*)&Bh_s[r][c8] = *(const float4*)&Bh[goB];
            *(float4*)&Bl_s[r][c8] = *(const float4*)&Bl[goB];
        }
        __syncthreads();

#pragma unroll
        for (int kk = 0; kk < BK; kk += 16) {
            uint32_t ah[4][4], al[4][4], bh[4][2], bl[4][2];
#pragma unroll
            for (int mi = 0; mi < 4; mi++) {
                int row = wm * 64 + mi * 16 + a_row_off;
                uint32_t ad = smem_u32(&Ah_s[row][kk + a_col_off]);
                ldsm_x4(ah[mi][0], ah[mi][1], ah[mi][2], ah[mi][3], ad);
                uint32_t ad2 = smem_u32(&Al_s[row][kk + a_col_off]);
                ldsm_x4(al[mi][0], al[mi][1], al[mi][2], al[mi][3], ad2);
            }
#pragma unroll
            for (int ng = 0; ng < 2; ng++) {
                int row = wn * 32 + ng * 16 + b_row_off;
                uint32_t bd = smem_u32(&Bh_s[row][kk + b_col_off]);
                ldsm_x4(bh[ng*2][0], bh[ng*2][1], bh[ng*2+1][0], bh[ng*2+1][1], bd);
                uint32_t bd2 = smem_u32(&Bl_s[row][kk + b_col_off]);
                ldsm_x4(bl[ng*2][0], bl[ng*2][1], bl[ng*2+1][0], bl[ng*2+1][1], bd2);
            }
#pragma unroll
            for (int mi = 0; mi < 4; mi++)
#pragma unroll
                for (int ni = 0; ni < 4; ni++) {
                    mma_bf16(acc[mi][ni], ah[mi], bh[ni]);
                    mma_bf16(acc[mi][ni], ah[mi], bl[ni]);
                    mma_bf16(acc[mi][ni], al[mi], bh[ni]);
                }
        }
        __syncthreads();
    }

    const float pa = prelu ? *prelu : 0.f;
#pragma unroll
    for (int mi = 0; mi < 4; mi++) {
#pragma unroll
        for (int ni = 0; ni < 4; ni++) {
            int row0 = m0 + wm * 64 + mi * 16 + (lane >> 2);
            int col  = n0 + wn * 32 + ni * 8 + (lane & 3) * 2;
#pragma unroll
            for (int half = 0; half < 2; half++) {
                int row = row0 + half * 8;
                float v0 = acc[mi][ni][half * 2 + 0];
                float v1 = acc[mi][ni][half * 2 + 1];
                if (bias) { v0 += bias[col]; v1 += bias[col + 1]; }
                if (prelu) {
                    v0 = (v0 >= 0.f) ? v0 : pa * v0;
                    v1 = (v1 >= 0.f) ? v1 : pa * v1;
                }
                size_t o = (size_t)row * N + col;
                if (Cf) *(float2*)&Cf[o] = make_float2(v0, v1);
                if (Ch) {
                    uint32_t hh2, ll2;
                    pack2(v0, v1, hh2, ll2);
                    *(uint32_t*)&Ch[o] = hh2;
                    *(uint32_t*)&Cl[o] = ll2;
                }
            }
        }
    }
}

// ---------------- Flash attention v2 (mma.sync, register softmax) ----------
// BM=128 q rows, BN=64 keys, 8 warps; warp w owns q rows [16w, 16w+16).
// S and O via split-bf16 3-pass mma; P stays in registers (C->A frag remap).
#define FSTR 72   /* bf16 row stride: 144B = 9*16B, ldmatrix conflict-free */

struct Fa2Smem {
    bf16 Qh[128][FSTR], Ql[128][FSTR];
    bf16 Kh[64][FSTR],  Kl[64][FSTR];
    bf16 Vth[64][FSTR], Vtl[64][FSTR];   // transposed: [d][key]
};

__global__ __launch_bounds__(256) void flash_attn2(const float* __restrict__ qkv,
                                                   bf16* __restrict__ out_h,
                                                   bf16* __restrict__ out_l)
{
    extern __shared__ char smem_raw[];
    Fa2Smem& S = *(Fa2Smem*)smem_raw;
    const int tid  = threadIdx.x;
    const int lane = tid & 31;
    const int wid  = tid >> 5;
    const int b  = blockIdx.y >> 4, h = blockIdx.y & 15;
    const int q0 = blockIdx.x * 128;
    const float scale = 0.125f;

    const int mat = lane >> 3, rin = lane & 7;
    const int a_row_off = (mat & 1) * 8 + rin;
    const int a_col_off = (mat >> 1) * 8;
    const int b_row_off = (mat >> 1) * 8 + rin;
    const int b_col_off = (mat & 1) * 8;

    // load Q tile (scaled), split hi/lo
    for (int idx = tid; idx < 128 * 16; idx += 256) {
        int r = idx >> 4, f = idx & 15;
        float4 v = *(const float4*)&qkv[(size_t)(b*SEQ + q0 + r)*QKVN + h*HD + f*4];
        bf16 h0,l0,h1,l1,h2,l2,h3,l3;
        split2(v.x*scale,h0,l0); split2(v.y*scale,h1,l1);
        split2(v.z*scale,h2,l2); split2(v.w*scale,h3,l3);
        S.Qh[r][f*4+0]=h0; S.Qh[r][f*4+1]=h1; S.Qh[r][f*4+2]=h2; S.Qh[r][f*4+3]=h3;
        S.Ql[r][f*4+0]=l0; S.Ql[r][f*4+1]=l1; S.Ql[r][f*4+2]=l2; S.Ql[r][f*4+3]=l3;
    }

    float m_[2] = {-1e30f, -1e30f};
    float l_[2] = {0.f, 0.f};
    float o[8][4];
#pragma unroll
    for (int i = 0; i < 8; i++)
#pragma unroll
        for (int j = 0; j < 4; j++) o[i][j] = 0.f;

    for (int kv0 = 0; kv0 < SEQ; kv0 += 64) {
        __syncthreads();   // protects K/V smem reuse (and Q before first use)
        // load K [key][d] and V transposed [d][key], split hi/lo
        for (int idx = tid; idx < 64 * 16; idx += 256) {
            int c = idx >> 4, f = idx & 15;
            const float* base = &qkv[(size_t)(b*SEQ + kv0 + c)*QKVN + h*HD + f*4];
            float4 kv = *(const float4*)(base + DIM);
            bf16 h0,l0,h1,l1,h2,l2,h3,l3;
            split2(kv.x,h0,l0); split2(kv.y,h1,l1); split2(kv.z,h2,l2); split2(kv.w,h3,l3);
            S.Kh[c][f*4+0]=h0; S.Kh[c][f*4+1]=h1; S.Kh[c][f*4+2]=h2; S.Kh[c][f*4+3]=h3;
            S.Kl[c][f*4+0]=l0; S.Kl[c][f*4+1]=l1; S.Kl[c][f*4+2]=l2; S.Kl[c][f*4+3]=l3;
            float4 vv = *(const float4*)(base + 2*DIM);
            split2(vv.x,h0,l0); split2(vv.y,h1,l1); split2(vv.z,h2,l2); split2(vv.w,h3,l3);
            S.Vth[f*4+0][c]=h0; S.Vth[f*4+1][c]=h1; S.Vth[f*4+2][c]=h2; S.Vth[f*4+3][c]=h3;
            S.Vtl[f*4+0][c]=l0; S.Vtl[f*4+1][c]=l1; S.Vtl[f*4+2][c]=l2; S.Vtl[f*4+3][c]=l3;
        }
        __syncthreads();

        // S = Q K^T : warp tile 16 x 64
        float s[8][4];
#pragma unroll
        for (int i = 0; i < 8; i++)
#pragma unroll
            for (int j = 0; j < 4; j++) s[i][j] = 0.f;
#pragma unroll
        for (int ks = 0; ks < 4; ks++) {
            int kk = ks * 16;
            uint32_t ah[4], al2[4], bh[8][2], bl[8][2];
            uint32_t ad = smem_u32(&S.Qh[wid*16 + a_row_off][kk + a_col_off]);
            ldsm_x4(ah[0], ah[1], ah[2], ah[3], ad);
            uint32_t ad2 = smem_u32(&S.Ql[wid*16 + a_row_off][kk + a_col_off]);
            ldsm_x4(al2[0], al2[1], al2[2], al2[3], ad2);
#pragma unroll
            for (int ng = 0; ng < 4; ng++) {
                uint32_t bd = smem_u32(&S.Kh[ng*16 + b_row_off][kk + b_col_off]);
                ldsm_x4(bh[ng*2][0], bh[ng*2][1], bh[ng*2+1][0], bh[ng*2+1][1], bd);
                uint32_t bd2 = smem_u32(&S.Kl[ng*16 + b_row_off][kk + b_col_off]);
                ldsm_x4(bl[ng*2][0], bl[ng*2][1], bl[ng*2+1][0], bl[ng*2+1][1], bd2);
            }
#pragma unroll
            for (int ni = 0; ni < 8; ni++) {
                mma_bf16(s[ni], ah, bh[ni]);
                mma_bf16(s[ni], ah, bl[ni]);
                mma_bf16(s[ni], al2, bh[ni]);
            }
        }

        // online softmax in registers (rows r=lane>>2 [half 0], r+8 [half 1])
#pragma unroll
        for (int half = 0; half < 2; half++) {
            float mloc = -1e30f;
#pragma unroll
            for (int ni = 0; ni < 8; ni++) {
                mloc = fmaxf(mloc, s[ni][half*2+0]);
                mloc = fmaxf(mloc, s[ni][half*2+1]);
            }
            mloc = fmaxf(mloc, __shfl_xor_sync(0xffffffffu, mloc, 1));
            mloc = fmaxf(mloc, __shfl_xor_sync(0xffffffffu, mloc, 2));
            float mnew = fmaxf(m_[half], mloc);
            float alf = __expf(m_[half] - mnew);
            m_[half] = mnew;
            float ps = 0.f;
#pragma unroll
            for (int ni = 0; ni < 8; ni++) {
                float p0 = __expf(s[ni][half*2+0] - mnew);
                float p1 = __expf(s[ni][half*2+1] - mnew);
                s[ni][half*2+0] = p0; s[ni][half*2+1] = p1;
                ps += p0 + p1;
            }
            ps += __shfl_xor_sync(0xffffffffu, ps, 1);
            ps += __shfl_xor_sync(0xffffffffu, ps, 2);
            l_[half] = l_[half] * alf + ps;
#pragma unroll
            for (int ni = 0; ni < 8; ni++) {
                o[ni][half*2+0] *= alf;
                o[ni][half*2+1] *= alf;
            }
        }

        // O += P V : remap S C-frags -> A-frags, B from transposed V
#pragma unroll
        for (int ks = 0; ks < 4; ks++) {
            uint32_t pah[4], pal[4];
            pack2(s[2*ks][0],   s[2*ks][1],   pah[0], pal[0]);
            pack2(s[2*ks][2],   s[2*ks][3],   pah[1], pal[1]);
            pack2(s[2*ks+1][0], s[2*ks+1][1], pah[2], pal[2]);
            pack2(s[2*ks+1][2], s[2*ks+1][3], pah[3], pal[3]);
            uint32_t bh[8][2], bl[8][2];
#pragma unroll
            for (int ng = 0; ng < 4; ng++) {
                uint32_t bd = smem_u32(&S.Vth[ng*16 + b_row_off][ks*16 + b_col_off]);
                ldsm_x4(bh[ng*2][0], bh[ng*2][1], bh[ng*2+1][0], bh[ng*2+1][1], bd);
                uint32_t bd2 = smem_u32(&S.Vtl[ng*16 + b_row_off][ks*16 + b_col_off]);
                ldsm_x4(bl[ng*2][0], bl[ng*2][1], bl[ng*2+1][0], bl[ng*2+1][1], bd2);
            }
#pragma unroll
            for (int ni = 0; ni < 8; ni++) {
                mma_bf16(o[ni], pah, bh[ni]);
                mma_bf16(o[ni], pah, bl[ni]);
                mma_bf16(o[ni], pal, bh[ni]);
            }
        }
    }

    // epilogue: normalize, split, store bf16 hi/lo
    float inv0 = 1.f / l_[0], inv1 = 1.f / l_[1];
#pragma unroll
    for (int ni = 0; ni < 8; ni++) {
        int col = ni * 8 + (lane & 3) * 2;
#pragma unroll
        for (int half = 0; half < 2; half++) {
            float inv = half ? inv1 : inv0;
            int row = q0 + wid * 16 + (lane >> 2) + half * 8;
            float v0 = o[ni][half*2+0] * inv;
            float v1 = o[ni][half*2+1] * inv;
            uint32_t hh2, ll2;
            pack2(v0, v1, hh2, ll2);
            size_t base = (size_t)(b*SEQ + row)*DIM + h*HD + col;
            *(uint32_t*)&out_h[base] = hh2;
            *(uint32_t*)&out_l[base] = ll2;
        }
    }
}

// ---------------- residual add + LayerNorm ---------------------------------
__global__ __launch_bounds__(256) void add_ln(
    const float* __restrict__ a, const float* __restrict__ bres,
    const float* __restrict__ g, const float* __restrict__ beta,
    float* __restrict__ out, bf16* __restrict__ out_h, bf16* __restrict__ out_l)
{
    const int row = blockIdx.x;
    const int tid = threadIdx.x;
    float4 av = *(const float4*)&a   [(size_t)row*DIM + tid*4];
    float4 bv = *(const float4*)&bres[(size_t)row*DIM + tid*4];
    float v[4] = {av.x+bv.x, av.y+bv.y, av.z+bv.z, av.w+bv.w};
    float s  = v[0]+v[1]+v[2]+v[3];
    float sq = v[0]*v[0]+v[1]*v[1]+v[2]*v[2]+v[3]*v[3];

    __shared__ float rs[256], rq[256];
    rs[tid] = s; rq[tid] = sq;
    __syncthreads();
    for (int off = 128; off > 0; off >>= 1) {
        if (tid < off) { rs[tid] += rs[tid+off]; rq[tid] += rq[tid+off]; }
        __syncthreads();
    }
    float mean = rs[0] * (1.f/DIM);
    float var  = rq[0] * (1.f/DIM) - mean*mean;
    float rstd = rsqrtf(var + 1e-5f);

    float4 gv = *(const float4*)&g[tid*4];
    float4 ev = *(const float4*)&beta[tid*4];
    float ov[4];
    ov[0] = (v[0]-mean)*rstd*gv.x + ev.x;
    ov[1] = (v[1]-mean)*rstd*gv.y + ev.y;
    ov[2] = (v[2]-mean)*rstd*gv.z + ev.z;
    ov[3] = (v[3]-mean)*rstd*gv.w + ev.w;
    *(float4*)&out[(size_t)row*DIM + tid*4] = make_float4(ov[0],ov[1],ov[2],ov[3]);
    if (out_h) {
        uint32_t h01, l01, h23, l23;
        pack2(ov[0], ov[1], h01, l01);
        pack2(ov[2], ov[3], h23, l23);
        size_t base = (size_t)row*DIM + tid*4;
        *(uint32_t*)&out_h[base]   = h01;
        *(uint32_t*)&out_h[base+2] = h23;
        *(uint32_t*)&out_l[base]   = l01;
        *(uint32_t*)&out_l[base+2] = l23;
    }
}

// ---------------- launch ---------------------------------------------------
extern "C" void kernel_launch(void* const* d_in, const int* in_sizes, int n_in,
                              void* d_out, int out_size)
{
    (void)in_sizes; (void)n_in; (void)out_size;
    const float* x       = (const float*)d_in[0];
    const float* qkv_w   = (const float*)d_in[1];
    const float* proj_w  = (const float*)d_in[2];
    const float* proj_b  = (const float*)d_in[3];
    const float* ln1_g   = (const float*)d_in[4];
    const float* ln1_b   = (const float*)d_in[5];
    const float* w1      = (const float*)d_in[6];
    const float* b1      = (const float*)d_in[7];
    const float* prelu_a = (const float*)d_in[8];
    const float* w2      = (const float*)d_in[9];
    const float* b2      = (const float*)d_in[10];
    const float* ln2_g   = (const float*)d_in[11];
    const float* ln2_b   = (const float*)d_in[12];
    float* out = (float*)d_out;

    float *qkv, *x1, *tmp;
    bf16 *xh,*xl,*ah,*al,*x1h,*x1l,*hh,*hl,*wqh,*wql,*wph,*wpl,*w1h,*w1l,*w2h,*w2l;
    cudaGetSymbolAddress((void**)&qkv, g_qkv);
    cudaGetSymbolAddress((void**)&x1,  g_x1);
    cudaGetSymbolAddress((void**)&tmp, g_tmp);
    cudaGetSymbolAddress((void**)&xh,  g_xh);  cudaGetSymbolAddress((void**)&xl,  g_xl);
    cudaGetSymbolAddress((void**)&ah,  g_ah);  cudaGetSymbolAddress((void**)&al,  g_al);
    cudaGetSymbolAddress((void**)&x1h, g_x1h); cudaGetSymbolAddress((void**)&x1l, g_x1l);
    cudaGetSymbolAddress((void**)&hh,  g_hh);  cudaGetSymbolAddress((void**)&hl,  g_hl);
    cudaGetSymbolAddress((void**)&wqh, g_wqh); cudaGetSymbolAddress((void**)&wql, g_wql);
    cudaGetSymbolAddress((void**)&wph, g_wph); cudaGetSymbolAddress((void**)&wpl, g_wpl);
    cudaGetSymbolAddress((void**)&w1h, g_w1h); cudaGetSymbolAddress((void**)&w1l, g_w1l);
    cudaGetSymbolAddress((void**)&w2h, g_w2h); cudaGetSymbolAddress((void**)&w2l, g_w2l);

    const dim3 blk(256);
    const int fasz = (int)sizeof(Fa2Smem);
    cudaFuncSetAttribute(flash_attn2, cudaFuncAttributeMaxDynamicSharedMemorySize, fasz);

    // splits (inputs + weights)
    split_bf16<<<(MROWS*DIM)/1024, blk>>>(x, xh, xl);
    split_bf16<<<(QKVN*DIM)/1024, blk>>>(qkv_w, wqh, wql);
    split_bf16<<<(DIM*DIM)/1024,  blk>>>(proj_w, wph, wpl);
    split_bf16<<<(HID*DIM)/1024,  blk>>>(w1, w1h, w1l);
    split_bf16<<<(DIM*HID)/1024,  blk>>>(w2, w2h, w2l);

    // 1) qkv = x @ qkv_w^T (fp32 out for attention)
    gemm_mma<<<dim3(QKVN/128, MROWS/128), blk>>>(
        xh, xl, wqh, wql, nullptr, nullptr, qkv, nullptr, nullptr, MROWS, QKVN, DIM);
    // 2) attention -> bf16 hi/lo
    flash_attn2<<<dim3(SEQ/128, B_SZ*HEADS), blk, fasz>>>(qkv, ah, al);
    // 3) proj -> tmp fp32
    gemm_mma<<<dim3(DIM/128, MROWS/128), blk>>>(
        ah, al, wph, wpl, proj_b, nullptr, tmp, nullptr, nullptr, MROWS, DIM, DIM);
    // 4) x1 = LN(x + proj), also split
    add_ln<<<MROWS, blk>>>(x, tmp, ln1_g, ln1_b, x1, x1h, x1l);
    // 5) h = PReLU(x1 @ w1^T + b1) -> bf16 hi/lo only
    gemm_mma<<<dim3(HID/128, MROWS/128), blk>>>(
        x1h, x1l, w1h, w1l, b1, prelu_a, nullptr, hh, hl, MROWS, HID, DIM);
    // 6) h2 = h @ w2^T + b2 -> tmp fp32
    gemm_mma<<<dim3(DIM/128, MROWS/128), blk>>>(
        hh, hl, w2h, w2l, b2, nullptr, tmp, nullptr, nullptr, MROWS, DIM, HID);
    // 7) out = LN(x1 + h2)
    add_ln<<<MROWS, blk>>>(x1, tmp, ln2_g, ln2_b, out, nullptr, nullptr);
}

// round 6
// speedup vs baseline: 2.2441x; 1.0988x over previous
#include <cuda_runtime.h>
#include <cuda_bf16.h>
#include <cstdint>
#include <math.h>

#define B_SZ 4
#define SEQ  2048
#define DIM  1024
#define HEADS 16
#define HD   64
#define HID  4096
#define MROWS (B_SZ*SEQ)   /* 8192 */
#define QKVN  (3*DIM)      /* 3072 */

typedef __nv_bfloat16 bf16;

// ---------------- scratch (static device globals; no runtime alloc) --------
__device__ bf16  g_qkvh[(size_t)MROWS*QKVN];
__device__ bf16  g_qkvl[(size_t)MROWS*QKVN];
__device__ float g_x1  [(size_t)MROWS*DIM];
__device__ float g_tmp [(size_t)MROWS*DIM];
__device__ bf16  g_xh  [(size_t)MROWS*DIM];
__device__ bf16  g_xl  [(size_t)MROWS*DIM];
__device__ bf16  g_ah  [(size_t)MROWS*DIM];
__device__ bf16  g_al  [(size_t)MROWS*DIM];
__device__ bf16  g_x1h [(size_t)MROWS*DIM];
__device__ bf16  g_x1l [(size_t)MROWS*DIM];
__device__ bf16  g_hh  [(size_t)MROWS*HID];
__device__ bf16  g_hl  [(size_t)MROWS*HID];
__device__ bf16  g_wqh [(size_t)QKVN*DIM];
__device__ bf16  g_wql [(size_t)QKVN*DIM];
__device__ bf16  g_wph [(size_t)DIM*DIM];
__device__ bf16  g_wpl [(size_t)DIM*DIM];
__device__ bf16  g_w1h [(size_t)HID*DIM];
__device__ bf16  g_w1l [(size_t)HID*DIM];
__device__ bf16  g_w2h [(size_t)DIM*HID];
__device__ bf16  g_w2l [(size_t)DIM*HID];

// ---------------- helpers ---------------------------------------------------
__device__ __forceinline__ uint32_t smem_u32(const void* p) {
    uint32_t a;
    asm("{ .reg .u64 t; cvta.to.shared.u64 t, %1; cvt.u32.u64 %0, t; }" : "=r"(a) : "l"(p));
    return a;
}
__device__ __forceinline__ void ldsm_x4(uint32_t& r0, uint32_t& r1, uint32_t& r2,
                                        uint32_t& r3, uint32_t addr) {
    asm volatile("ldmatrix.sync.aligned.m8n8.x4.shared.b16 {%0,%1,%2,%3}, [%4];"
                 : "=r"(r0), "=r"(r1), "=r"(r2), "=r"(r3) : "r"(addr));
}
__device__ __forceinline__ void mma_bf16(float* c, const uint32_t* a, const uint32_t* b) {
    asm volatile("mma.sync.aligned.m16n8k16.row.col.f32.bf16.bf16.f32 "
                 "{%0,%1,%2,%3}, {%4,%5,%6,%7}, {%8,%9}, {%0,%1,%2,%3};"
                 : "+f"(c[0]), "+f"(c[1]), "+f"(c[2]), "+f"(c[3])
                 : "r"(a[0]), "r"(a[1]), "r"(a[2]), "r"(a[3]), "r"(b[0]), "r"(b[1]));
}
__device__ __forceinline__ void cp_async16(uint32_t s, const void* g) {
    asm volatile("cp.async.cg.shared.global [%0], [%1], 16;" :: "r"(s), "l"(g));
}
#define CP_COMMIT() asm volatile("cp.async.commit_group;")
#define CP_WAIT(n)  asm volatile("cp.async.wait_group %0;" :: "n"(n))

__device__ __forceinline__ void split2(float v, bf16& h, bf16& l) {
    h = __float2bfloat16(v);
    l = __float2bfloat16(v - __bfloat162float(h));
}
__device__ __forceinline__ void pack2(float a, float b, uint32_t& h, uint32_t& l) {
    bf16 ha = __float2bfloat16(a), hb = __float2bfloat16(b);
    bf16 la = __float2bfloat16(a - __bfloat162float(ha));
    bf16 lb = __float2bfloat16(b - __bfloat162float(hb));
    __nv_bfloat162 H; H.x = ha; H.y = hb;
    __nv_bfloat162 L; L.x = la; L.y = lb;
    h = *(uint32_t*)&H; l = *(uint32_t*)&L;
}

// ---------------- fp32 -> bf16 hi/lo split ----------------------------------
__global__ __launch_bounds__(256) void split_bf16(
    const float* __restrict__ src, bf16* __restrict__ hi, bf16* __restrict__ lo)
{
    size_t i = ((size_t)blockIdx.x * 256 + threadIdx.x) * 4;
    float4 v = *(const float4*)&src[i];
    uint32_t h01, l01, h23, l23;
    pack2(v.x, v.y, h01, l01);
    pack2(v.z, v.w, h23, l23);
    *(uint32_t*)&hi[i]   = h01; *(uint32_t*)&hi[i+2] = h23;
    *(uint32_t*)&lo[i]   = l01; *(uint32_t*)&lo[i+2] = l23;
}

// ---------------- split-bf16 GEMM, cp.async double-buffered ------------------
#define BK   32
#define APAD 8
#define LDS_W (BK + APAD)          /* 40 bf16 = 80B */
#define ARR   (128 * LDS_W)        /* elements per operand array */
#define STG   (4 * ARR)            /* elements per stage */
#define GEMM_SMEM (2 * STG * 2)    /* bytes: 81920 */

__global__ __launch_bounds__(256) void gemm_mma(
    const bf16* __restrict__ Ah, const bf16* __restrict__ Al,
    const bf16* __restrict__ Bh, const bf16* __restrict__ Bl,
    const float* __restrict__ bias, const float* __restrict__ prelu,
    float* __restrict__ Cf, bf16* __restrict__ Ch, bf16* __restrict__ Cl,
    int M, int N, int K)
{
    extern __shared__ bf16 smem_g[];

    const int tid  = threadIdx.x;
    const int lane = tid & 31;
    const int wid  = tid >> 5;
    const int wm   = wid & 1;
    const int wn   = wid >> 1;
    const int m0   = blockIdx.y * 128;
    const int n0   = blockIdx.x * 128;

    // per-thread load coords: 2 float4 per array per chunk
    const int lr0 = tid >> 2, lc0 = (tid & 3) * 8;          // v=0
    const int lr1 = (tid + 256) >> 2;                        // v=1 (same lc)

    float acc[4][4][4];
#pragma unroll
    for (int i = 0; i < 4; i++)
#pragma unroll
        for (int j = 0; j < 4; j++)
#pragma unroll
            for (int r = 0; r < 4; r++) acc[i][j][r] = 0.f;

    const int mat = lane >> 3, rin = lane & 7;
    const int a_row_off = (mat & 1) * 8 + rin;
    const int a_col_off = (mat >> 1) * 8;
    const int b_row_off = (mat >> 1) * 8 + rin;
    const int b_col_off = (mat & 1) * 8;

    const int nchunk = K / BK;

    // -- issue loads for chunk c into stage s
    auto issue = [&](int s, int c) {
        const int k0 = c * BK;
        bf16* base = smem_g + s * STG;
        uint32_t sA_h = smem_u32(base + lr0 * LDS_W + lc0);
        uint32_t sA_h2= smem_u32(base + lr1 * LDS_W + lc0);
        cp_async16(sA_h,            &Ah[(size_t)(m0 + lr0) * K + k0 + lc0]);
        cp_async16(sA_h2,           &Ah[(size_t)(m0 + lr1) * K + k0 + lc0]);
        cp_async16(sA_h  + 2*ARR,   &Al[(size_t)(m0 + lr0) * K + k0 + lc0]);
        cp_async16(sA_h2 + 2*ARR,   &Al[(size_t)(m0 + lr1) * K + k0 + lc0]);
        cp_async16(sA_h  + 4*ARR,   &Bh[(size_t)(n0 + lr0) * K + k0 + lc0]);
        cp_async16(sA_h2 + 4*ARR,   &Bh[(size_t)(n0 + lr1) * K + k0 + lc0]);
        cp_async16(sA_h  + 6*ARR,   &Bl[(size_t)(n0 + lr0) * K + k0 + lc0]);
        cp_async16(sA_h2 + 6*ARR,   &Bl[(size_t)(n0 + lr1) * K + k0 + lc0]);
        CP_COMMIT();
    };

    issue(0, 0);

    for (int c = 0; c < nchunk; c++) {
        const int s = c & 1;
        if (c + 1 < nchunk) {
            issue(s ^ 1, c + 1);
            CP_WAIT(1);
        } else {
            CP_WAIT(0);
        }
        __syncthreads();

        bf16 (*Ah_s)[LDS_W] = (bf16(*)[LDS_W])(smem_g + s * STG);
        bf16 (*Al_s)[LDS_W] = (bf16(*)[LDS_W])(smem_g + s * STG + ARR);
        bf16 (*Bh_s)[LDS_W] = (bf16(*)[LDS_W])(smem_g + s * STG + 2 * ARR);
        bf16 (*Bl_s)[LDS_W] = (bf16(*)[LDS_W])(smem_g + s * STG + 3 * ARR);

#pragma unroll
        for (int kk = 0; kk < BK; kk += 16) {
            uint32_t ah[4][4], al[4][4], bh[4][2], bl[4][2];
#pragma unroll
            for (int mi = 0; mi < 4; mi++) {
                int row = wm * 64 + mi * 16 + a_row_off;
                ldsm_x4(ah[mi][0], ah[mi][1], ah[mi][2], ah[mi][3],
                        smem_u32(&Ah_s[row][kk + a_col_off]));
                ldsm_x4(al[mi][0], al[mi][1], al[mi][2], al[mi][3],
                        smem_u32(&Al_s[row][kk + a_col_off]));
            }
#pragma unroll
            for (int ng = 0; ng < 2; ng++) {
                int row = wn * 32 + ng * 16 + b_row_off;
                ldsm_x4(bh[ng*2][0], bh[ng*2][1], bh[ng*2+1][0], bh[ng*2+1][1],
                        smem_u32(&Bh_s[row][kk + b_col_off]));
                ldsm_x4(bl[ng*2][0], bl[ng*2][1], bl[ng*2+1][0], bl[ng*2+1][1],
                        smem_u32(&Bl_s[row][kk + b_col_off]));
            }
#pragma unroll
            for (int mi = 0; mi < 4; mi++)
#pragma unroll
                for (int ni = 0; ni < 4; ni++) {
                    mma_bf16(acc[mi][ni], ah[mi], bh[ni]);
                    mma_bf16(acc[mi][ni], ah[mi], bl[ni]);
                    mma_bf16(acc[mi][ni], al[mi], bh[ni]);
                }
        }
        __syncthreads();
    }

    const float pa = prelu ? *prelu : 0.f;
#pragma unroll
    for (int mi = 0; mi < 4; mi++) {
#pragma unroll
        for (int ni = 0; ni < 4; ni++) {
            int row0 = m0 + wm * 64 + mi * 16 + (lane >> 2);
            int col  = n0 + wn * 32 + ni * 8 + (lane & 3) * 2;
#pragma unroll
            for (int half = 0; half < 2; half++) {
                int row = row0 + half * 8;
                float v0 = acc[mi][ni][half * 2 + 0];
                float v1 = acc[mi][ni][half * 2 + 1];
                if (bias) { v0 += bias[col]; v1 += bias[col + 1]; }
                if (prelu) {
                    v0 = (v0 >= 0.f) ? v0 : pa * v0;
                    v1 = (v1 >= 0.f) ? v1 : pa * v1;
                }
                size_t o = (size_t)row * N + col;
                if (Cf) *(float2*)&Cf[o] = make_float2(v0, v1);
                if (Ch) {
                    uint32_t hh2, ll2;
                    pack2(v0, v1, hh2, ll2);
                    *(uint32_t*)&Ch[o] = hh2;
                    *(uint32_t*)&Cl[o] = ll2;
                }
            }
        }
    }
}

// ---------------- Flash attention v2 (bf16 in, mma.sync, reg softmax) -------
#define FSTR 72

struct Fa2Smem {
    bf16 Qh[128][FSTR], Ql[128][FSTR];
    bf16 Kh[64][FSTR],  Kl[64][FSTR];
    bf16 Vth[64][FSTR], Vtl[64][FSTR];
};

__global__ __launch_bounds__(256) void flash_attn2(
    const bf16* __restrict__ qh, const bf16* __restrict__ ql,
    bf16* __restrict__ out_h, bf16* __restrict__ out_l)
{
    extern __shared__ char smem_raw[];
    Fa2Smem& S = *(Fa2Smem*)smem_raw;
    const int tid  = threadIdx.x;
    const int lane = tid & 31;
    const int wid  = tid >> 5;
    const int b  = blockIdx.y >> 4, h = blockIdx.y & 15;
    const int q0 = blockIdx.x * 128;

    const int mat = lane >> 3, rin = lane & 7;
    const int a_row_off = (mat & 1) * 8 + rin;
    const int a_col_off = (mat >> 1) * 8;
    const int b_row_off = (mat >> 1) * 8 + rin;
    const int b_col_off = (mat & 1) * 8;

    __nv_bfloat162 sc2; sc2.x = __float2bfloat16(0.125f); sc2.y = sc2.x;

    // Q tile: straight bf16 copy, exact x0.125 scale on hi and lo
    for (int idx = tid; idx < 128 * 8; idx += 256) {
        int r = idx >> 3, f = idx & 7;
        size_t go = (size_t)(b*SEQ + q0 + r)*QKVN + h*HD + f*8;
        float4 vh = *(const float4*)&qh[go];
        float4 vl = *(const float4*)&ql[go];
        __nv_bfloat162* ph = (__nv_bfloat162*)&vh;
        __nv_bfloat162* pl = (__nv_bfloat162*)&vl;
#pragma unroll
        for (int j = 0; j < 4; j++) { ph[j] = __hmul2(ph[j], sc2); pl[j] = __hmul2(pl[j], sc2); }
        *(float4*)&S.Qh[r][f*8] = vh;
        *(float4*)&S.Ql[r][f*8] = vl;
    }

    float m_[2] = {-1e30f, -1e30f};
    float l_[2] = {0.f, 0.f};
    float o[8][4];
#pragma unroll
    for (int i = 0; i < 8; i++)
#pragma unroll
        for (int j = 0; j < 4; j++) o[i][j] = 0.f;

    for (int kv0 = 0; kv0 < SEQ; kv0 += 64) {
        __syncthreads();
        // K: straight copy; V: transpose scatter
        for (int idx = tid; idx < 64 * 8; idx += 256) {
            int c = idx >> 3, f = idx & 7;
            size_t go = (size_t)(b*SEQ + kv0 + c)*QKVN + h*HD + f*8;
            *(float4*)&S.Kh[c][f*8] = *(const float4*)&qh[go + DIM];
            *(float4*)&S.Kl[c][f*8] = *(const float4*)&ql[go + DIM];
            float4 vh = *(const float4*)&qh[go + 2*DIM];
            float4 vl = *(const float4*)&ql[go + 2*DIM];
            const bf16* eh = (const bf16*)&vh;
            const bf16* el = (const bf16*)&vl;
#pragma unroll
            for (int j = 0; j < 8; j++) {
                S.Vth[f*8 + j][c] = eh[j];
                S.Vtl[f*8 + j][c] = el[j];
            }
        }
        __syncthreads();

        // S = Q K^T
        float s[8][4];
#pragma unroll
        for (int i = 0; i < 8; i++)
#pragma unroll
            for (int j = 0; j < 4; j++) s[i][j] = 0.f;
#pragma unroll
        for (int ks = 0; ks < 4; ks++) {
            int kk = ks * 16;
            uint32_t ah[4], al2[4], bh[8][2], bl[8][2];
            ldsm_x4(ah[0], ah[1], ah[2], ah[3],
                    smem_u32(&S.Qh[wid*16 + a_row_off][kk + a_col_off]));
            ldsm_x4(al2[0], al2[1], al2[2], al2[3],
                    smem_u32(&S.Ql[wid*16 + a_row_off][kk + a_col_off]));
#pragma unroll
            for (int ng = 0; ng < 4; ng++) {
                ldsm_x4(bh[ng*2][0], bh[ng*2][1], bh[ng*2+1][0], bh[ng*2+1][1],
                        smem_u32(&S.Kh[ng*16 + b_row_off][kk + b_col_off]));
                ldsm_x4(bl[ng*2][0], bl[ng*2][1], bl[ng*2+1][0], bl[ng*2+1][1],
                        smem_u32(&S.Kl[ng*16 + b_row_off][kk + b_col_off]));
            }
#pragma unroll
            for (int ni = 0; ni < 8; ni++) {
                mma_bf16(s[ni], ah, bh[ni]);
                mma_bf16(s[ni], ah, bl[ni]);
                mma_bf16(s[ni], al2, bh[ni]);
            }
        }

        // online softmax in registers
#pragma unroll
        for (int half = 0; half < 2; half++) {
            float mloc = -1e30f;
#pragma unroll
            for (int ni = 0; ni < 8; ni++) {
                mloc = fmaxf(mloc, s[ni][half*2+0]);
                mloc = fmaxf(mloc, s[ni][half*2+1]);
            }
            mloc = fmaxf(mloc, __shfl_xor_sync(0xffffffffu, mloc, 1));
            mloc = fmaxf(mloc, __shfl_xor_sync(0xffffffffu, mloc, 2));
            float mnew = fmaxf(m_[half], mloc);
            float alf = __expf(m_[half] - mnew);
            m_[half] = mnew;
            float ps = 0.f;
#pragma unroll
            for (int ni = 0; ni < 8; ni++) {
                float p0 = __expf(s[ni][half*2+0] - mnew);
                float p1 = __expf(s[ni][half*2+1] - mnew);
                s[ni][half*2+0] = p0; s[ni][half*2+1] = p1;
                ps += p0 + p1;
            }
            ps += __shfl_xor_sync(0xffffffffu, ps, 1);
            ps += __shfl_xor_sync(0xffffffffu, ps, 2);
            l_[half] = l_[half] * alf + ps;
#pragma unroll
            for (int ni = 0; ni < 8; ni++) {
                o[ni][half*2+0] *= alf;
                o[ni][half*2+1] *= alf;
            }
        }

        // O += P V
#pragma unroll
        for (int ks = 0; ks < 4; ks++) {
            uint32_t pah[4], pal[4];
            pack2(s[2*ks][0],   s[2*ks][1],   pah[0], pal[0]);
            pack2(s[2*ks][2],   s[2*ks][3],   pah[1], pal[1]);
            pack2(s[2*ks+1][0], s[2*ks+1][1], pah[2], pal[2]);
            pack2(s[2*ks+1][2], s[2*ks+1][3], pah[3], pal[3]);
            uint32_t bh[8][2], bl[8][2];
#pragma unroll
            for (int ng = 0; ng < 4; ng++) {
                ldsm_x4(bh[ng*2][0], bh[ng*2][1], bh[ng*2+1][0], bh[ng*2+1][1],
                        smem_u32(&S.Vth[ng*16 + b_row_off][ks*16 + b_col_off]));
                ldsm_x4(bl[ng*2][0], bl[ng*2][1], bl[ng*2+1][0], bl[ng*2+1][1],
                        smem_u32(&S.Vtl[ng*16 + b_row_off][ks*16 + b_col_off]));
            }
#pragma unroll
            for (int ni = 0; ni < 8; ni++) {
                mma_bf16(o[ni], pah, bh[ni]);
                mma_bf16(o[ni], pah, bl[ni]);
                mma_bf16(o[ni], pal, bh[ni]);
            }
        }
    }

    float inv0 = 1.f / l_[0], inv1 = 1.f / l_[1];
#pragma unroll
    for (int ni = 0; ni < 8; ni++) {
        int col = ni * 8 + (lane & 3) * 2;
#pragma unroll
        for (int half = 0; half < 2; half++) {
            float inv = half ? inv1 : inv0;
            int row = q0 + wid * 16 + (lane >> 2) + half * 8;
            float v0 = o[ni][half*2+0] * inv;
            float v1 = o[ni][half*2+1] * inv;
            uint32_t hh2, ll2;
            pack2(v0, v1, hh2, ll2);
            size_t base = (size_t)(b*SEQ + row)*DIM + h*HD + col;
            *(uint32_t*)&out_h[base] = hh2;
            *(uint32_t*)&out_l[base] = ll2;
        }
    }
}

// ---------------- residual add + LayerNorm ---------------------------------
__global__ __launch_bounds__(256) void add_ln(
    const float* __restrict__ a, const float* __restrict__ bres,
    const float* __restrict__ g, const float* __restrict__ beta,
    float* __restrict__ out, bf16* __restrict__ out_h, bf16* __restrict__ out_l)
{
    const int row = blockIdx.x;
    const int tid = threadIdx.x;
    float4 av = *(const float4*)&a   [(size_t)row*DIM + tid*4];
    float4 bv = *(const float4*)&bres[(size_t)row*DIM + tid*4];
    float v[4] = {av.x+bv.x, av.y+bv.y, av.z+bv.z, av.w+bv.w};
    float s  = v[0]+v[1]+v[2]+v[3];
    float sq = v[0]*v[0]+v[1]*v[1]+v[2]*v[2]+v[3]*v[3];

    __shared__ float rs[256], rq[256];
    rs[tid] = s; rq[tid] = sq;
    __syncthreads();
    for (int off = 128; off > 0; off >>= 1) {
        if (tid < off) { rs[tid] += rs[tid+off]; rq[tid] += rq[tid+off]; }
        __syncthreads();
    }
    float mean = rs[0] * (1.f/DIM);
    float var  = rq[0] * (1.f/DIM) - mean*mean;
    float rstd = rsqrtf(var + 1e-5f);

    float4 gv = *(const float4*)&g[tid*4];
    float4 ev = *(const float4*)&beta[tid*4];
    float ov[4];
    ov[0] = (v[0]-mean)*rstd*gv.x + ev.x;
    ov[1] = (v[1]-mean)*rstd*gv.y + ev.y;
    ov[2] = (v[2]-mean)*rstd*gv.z + ev.z;
    ov[3] = (v[3]-mean)*rstd*gv.w + ev.w;
    *(float4*)&out[(size_t)row*DIM + tid*4] = make_float4(ov[0],ov[1],ov[2],ov[3]);
    if (out_h) {
        uint32_t h01, l01, h23, l23;
        pack2(ov[0], ov[1], h01, l01);
        pack2(ov[2], ov[3], h23, l23);
        size_t base = (size_t)row*DIM + tid*4;
        *(uint32_t*)&out_h[base]   = h01;
        *(uint32_t*)&out_h[base+2] = h23;
        *(uint32_t*)&out_l[base]   = l01;
        *(uint32_t*)&out_l[base+2] = l23;
    }
}

// ---------------- launch ---------------------------------------------------
extern "C" void kernel_launch(void* const* d_in, const int* in_sizes, int n_in,
                              void* d_out, int out_size)
{
    (void)in_sizes; (void)n_in; (void)out_size;
    const float* x       = (const float*)d_in[0];
    const float* qkv_w   = (const float*)d_in[1];
    const float* proj_w  = (const float*)d_in[2];
    const float* proj_b  = (const float*)d_in[3];
    const float* ln1_g   = (const float*)d_in[4];
    const float* ln1_b   = (const float*)d_in[5];
    const float* w1      = (const float*)d_in[6];
    const float* b1      = (const float*)d_in[7];
    const float* prelu_a = (const float*)d_in[8];
    const float* w2      = (const float*)d_in[9];
    const float* b2      = (const float*)d_in[10];
    const float* ln2_g   = (const float*)d_in[11];
    const float* ln2_b   = (const float*)d_in[12];
    float* out = (float*)d_out;

    float *x1, *tmp;
    bf16 *qkvh,*qkvl,*xh,*xl,*ah,*al,*x1h,*x1l,*hh,*hl;
    bf16 *wqh,*wql,*wph,*wpl,*w1h,*w1l,*w2h,*w2l;
    cudaGetSymbolAddress((void**)&qkvh, g_qkvh); cudaGetSymbolAddress((void**)&qkvl, g_qkvl);
    cudaGetSymbolAddress((void**)&x1,  g_x1);
    cudaGetSymbolAddress((void**)&tmp, g_tmp);
    cudaGetSymbolAddress((void**)&xh,  g_xh);  cudaGetSymbolAddress((void**)&xl,  g_xl);
    cudaGetSymbolAddress((void**)&ah,  g_ah);  cudaGetSymbolAddress((void**)&al,  g_al);
    cudaGetSymbolAddress((void**)&x1h, g_x1h); cudaGetSymbolAddress((void**)&x1l, g_x1l);
    cudaGetSymbolAddress((void**)&hh,  g_hh);  cudaGetSymbolAddress((void**)&hl,  g_hl);
    cudaGetSymbolAddress((void**)&wqh, g_wqh); cudaGetSymbolAddress((void**)&wql, g_wql);
    cudaGetSymbolAddress((void**)&wph, g_wph); cudaGetSymbolAddress((void**)&wpl, g_wpl);
    cudaGetSymbolAddress((void**)&w1h, g_w1h); cudaGetSymbolAddress((void**)&w1l, g_w1l);
    cudaGetSymbolAddress((void**)&w2h, g_w2h); cudaGetSymbolAddress((void**)&w2l, g_w2l);

    const dim3 blk(256);
    const int fasz = (int)sizeof(Fa2Smem);
    cudaFuncSetAttribute(flash_attn2, cudaFuncAttributeMaxDynamicSharedMemorySize, fasz);
    cudaFuncSetAttribute(gemm_mma, cudaFuncAttributeMaxDynamicSharedMemorySize, GEMM_SMEM);

    // splits (input + weights)
    split_bf16<<<(MROWS*DIM)/1024, blk>>>(x, xh, xl);
    split_bf16<<<(QKVN*DIM)/1024, blk>>>(qkv_w, wqh, wql);
    split_bf16<<<(DIM*DIM)/1024,  blk>>>(proj_w, wph, wpl);
    split_bf16<<<(HID*DIM)/1024,  blk>>>(w1, w1h, w1l);
    split_bf16<<<(DIM*HID)/1024,  blk>>>(w2, w2h, w2l);

    // 1) qkv = x @ qkv_w^T -> bf16 hi/lo directly
    gemm_mma<<<dim3(QKVN/128, MROWS/128), blk, GEMM_SMEM>>>(
        xh, xl, wqh, wql, nullptr, nullptr, nullptr, qkvh, qkvl, MROWS, QKVN, DIM);
    // 2) attention (bf16 in) -> bf16 hi/lo
    flash_attn2<<<dim3(SEQ/128, B_SZ*HEADS), blk, fasz>>>(qkvh, qkvl, ah, al);
    // 3) proj -> tmp fp32
    gemm_mma<<<dim3(DIM/128, MROWS/128), blk, GEMM_SMEM>>>(
        ah, al, wph, wpl, proj_b, nullptr, tmp, nullptr, nullptr, MROWS, DIM, DIM);
    // 4) x1 = LN(x + proj), also split
    add_ln<<<MROWS, blk>>>(x, tmp, ln1_g, ln1_b, x1, x1h, x1l);
    // 5) h = PReLU(x1 @ w1^T + b1) -> bf16 hi/lo only
    gemm_mma<<<dim3(HID/128, MROWS/128), blk, GEMM_SMEM>>>(
        x1h, x1l, w1h, w1l, b1, prelu_a, nullptr, hh, hl, MROWS, HID, DIM);
    // 6) h2 = h @ w2^T + b2 -> tmp fp32
    gemm_mma<<<dim3(DIM/128, MROWS/128), blk, GEMM_SMEM>>>(
        hh, hl, w2h, w2l, b2, nullptr, tmp, nullptr, nullptr, MROWS, DIM, HID);
    // 7) out = LN(x1 + h2)
    add_ln<<<MROWS, blk>>>(x1, tmp, ln2_g, ln2_b, out, nullptr, nullptr);
}

// round 8
// speedup vs baseline: 5.4623x; 2.4341x over previous
#include <cuda_runtime.h>
#include <cuda_fp16.h>
#include <cstdint>
#include <math.h>

#define B_SZ 4
#define SEQ  2048
#define DIM  1024
#define HEADS 16
#define HD   64
#define HID  4096
#define MROWS (B_SZ*SEQ)   /* 8192 */
#define QKVN  (3*DIM)      /* 3072 */

typedef __half f16;

// ---------------- scratch (static device globals; no runtime alloc) --------
__device__ f16   g_qkv [(size_t)MROWS*QKVN];
__device__ float g_x1  [(size_t)MROWS*DIM];
__device__ float g_tmp [(size_t)MROWS*DIM];
__device__ f16   g_xf  [(size_t)MROWS*DIM];
__device__ f16   g_af  [(size_t)MROWS*DIM];
__device__ f16   g_x1f [(size_t)MROWS*DIM];
__device__ f16   g_hf  [(size_t)MROWS*HID];
__device__ f16   g_wq  [(size_t)QKVN*DIM];
__device__ f16   g_wp  [(size_t)DIM*DIM];
__device__ f16   g_w1  [(size_t)HID*DIM];
__device__ f16   g_w2  [(size_t)DIM*HID];

// ---------------- helpers ---------------------------------------------------
__device__ __forceinline__ uint32_t smem_u32(const void* p) {
    uint32_t a;
    asm("{ .reg .u64 t; cvta.to.shared.u64 t, %1; cvt.u32.u64 %0, t; }" : "=r"(a) : "l"(p));
    return a;
}
__device__ __forceinline__ void ldsm_x4(uint32_t& r0, uint32_t& r1, uint32_t& r2,
                                        uint32_t& r3, uint32_t addr) {
    asm volatile("ldmatrix.sync.aligned.m8n8.x4.shared.b16 {%0,%1,%2,%3}, [%4];"
                 : "=r"(r0), "=r"(r1), "=r"(r2), "=r"(r3) : "r"(addr));
}
__device__ __forceinline__ void mma_f16(float* c, const uint32_t* a, const uint32_t* b) {
    asm volatile("mma.sync.aligned.m16n8k16.row.col.f32.f16.f16.f32 "
                 "{%0,%1,%2,%3}, {%4,%5,%6,%7}, {%8,%9}, {%0,%1,%2,%3};"
                 : "+f"(c[0]), "+f"(c[1]), "+f"(c[2]), "+f"(c[3])
                 : "r"(a[0]), "r"(a[1]), "r"(a[2]), "r"(a[3]), "r"(b[0]), "r"(b[1]));
}
__device__ __forceinline__ void cp_async16(uint32_t s, const void* g) {
    asm volatile("cp.async.cg.shared.global [%0], [%1], 16;" :: "r"(s), "l"(g));
}
#define CP_COMMIT() asm volatile("cp.async.commit_group;")
#define CP_WAIT(n)  asm volatile("cp.async.wait_group %0;" :: "n"(n))

__device__ __forceinline__ uint32_t packh2(float a, float b) {
    __half2 p = __floats2half2_rn(a, b);
    return *(uint32_t*)&p;
}

// ---------------- fp32 -> fp16 convert ---------------------------------------
__global__ __launch_bounds__(256) void to_f16(
    const float* __restrict__ src, f16* __restrict__ dst)
{
    size_t i = ((size_t)blockIdx.x * 256 + threadIdx.x) * 4;
    float4 v = *(const float4*)&src[i];
    uint32_t p01 = packh2(v.x, v.y);
    uint32_t p23 = packh2(v.z, v.w);
    *(uint32_t*)&dst[i]   = p01;
    *(uint32_t*)&dst[i+2] = p23;
}

// ---------------- fp16 GEMM, cp.async double-buffered ------------------------
// C[M,N] = A[M,K] @ B[N,K]^T (+bias)(+PReLU). fp32 accum.
// CTA 128x128, BK=32, 8 warps (2m x 4n), warp 64x32, m16n8k16.
#define BK   32
#define APAD 8
#define LDS_W (BK + APAD)          /* 40 halfs = 80B */
#define ARR   (128 * LDS_W)        /* elements per operand array */
#define STG   (2 * ARR)            /* elements per stage (A + B) */
#define GEMM_SMEM (2 * STG * 2)    /* bytes: 40960 */

__global__ __launch_bounds__(256) void gemm_f16(
    const f16* __restrict__ A, const f16* __restrict__ B,
    const float* __restrict__ bias, const float* __restrict__ prelu,
    float* __restrict__ Cf, f16* __restrict__ Ch,
    int M, int N, int K)
{
    extern __shared__ f16 smem_g[];

    const int tid  = threadIdx.x;
    const int lane = tid & 31;
    const int wid  = tid >> 5;
    const int wm   = wid & 1;
    const int wn   = wid >> 1;
    const int m0   = blockIdx.y * 128;
    const int n0   = blockIdx.x * 128;

    const int lr0 = tid >> 2, lc0 = (tid & 3) * 8;
    const int lr1 = (tid + 256) >> 2;

    float acc[4][4][4];
#pragma unroll
    for (int i = 0; i < 4; i++)
#pragma unroll
        for (int j = 0; j < 4; j++)
#pragma unroll
            for (int r = 0; r < 4; r++) acc[i][j][r] = 0.f;

    const int mat = lane >> 3, rin = lane & 7;
    const int a_row_off = (mat & 1) * 8 + rin;
    const int a_col_off = (mat >> 1) * 8;
    const int b_row_off = (mat >> 1) * 8 + rin;
    const int b_col_off = (mat & 1) * 8;

    const int nchunk = K / BK;

    auto issue = [&](int s, int c) {
        const int k0 = c * BK;
        f16* base = smem_g + s * STG;
        uint32_t s0 = smem_u32(base + lr0 * LDS_W + lc0);
        uint32_t s1 = smem_u32(base + lr1 * LDS_W + lc0);
        cp_async16(s0,           &A[(size_t)(m0 + lr0) * K + k0 + lc0]);
        cp_async16(s1,           &A[(size_t)(m0 + lr1) * K + k0 + lc0]);
        cp_async16(s0 + 2*ARR,   &B[(size_t)(n0 + lr0) * K + k0 + lc0]);
        cp_async16(s1 + 2*ARR,   &B[(size_t)(n0 + lr1) * K + k0 + lc0]);
        CP_COMMIT();
    };

    issue(0, 0);

    for (int c = 0; c < nchunk; c++) {
        const int s = c & 1;
        if (c + 1 < nchunk) {
            issue(s ^ 1, c + 1);
            CP_WAIT(1);
        } else {
            CP_WAIT(0);
        }
        __syncthreads();

        f16 (*A_s)[LDS_W] = (f16(*)[LDS_W])(smem_g + s * STG);
        f16 (*B_s)[LDS_W] = (f16(*)[LDS_W])(smem_g + s * STG + ARR);

#pragma unroll
        for (int kk = 0; kk < BK; kk += 16) {
            uint32_t a[4][4], b[4][2];
#pragma unroll
            for (int mi = 0; mi < 4; mi++) {
                int row = wm * 64 + mi * 16 + a_row_off;
                ldsm_x4(a[mi][0], a[mi][1], a[mi][2], a[mi][3],
                        smem_u32(&A_s[row][kk + a_col_off]));
            }
#pragma unroll
            for (int ng = 0; ng < 2; ng++) {
                int row = wn * 32 + ng * 16 + b_row_off;
                ldsm_x4(b[ng*2][0], b[ng*2][1], b[ng*2+1][0], b[ng*2+1][1],
                        smem_u32(&B_s[row][kk + b_col_off]));
            }
#pragma unroll
            for (int mi = 0; mi < 4; mi++)
#pragma unroll
                for (int ni = 0; ni < 4; ni++)
                    mma_f16(acc[mi][ni], a[mi], b[ni]);
        }
        __syncthreads();
    }

    const float pa = prelu ? *prelu : 0.f;
#pragma unroll
    for (int mi = 0; mi < 4; mi++) {
#pragma unroll
        for (int ni = 0; ni < 4; ni++) {
            int row0 = m0 + wm * 64 + mi * 16 + (lane >> 2);
            int col  = n0 + wn * 32 + ni * 8 + (lane & 3) * 2;
#pragma unroll
            for (int half_ = 0; half_ < 2; half_++) {
                int row = row0 + half_ * 8;
                float v0 = acc[mi][ni][half_ * 2 + 0];
                float v1 = acc[mi][ni][half_ * 2 + 1];
                if (bias) { v0 += bias[col]; v1 += bias[col + 1]; }
                if (prelu) {
                    v0 = (v0 >= 0.f) ? v0 : pa * v0;
                    v1 = (v1 >= 0.f) ? v1 : pa * v1;
                }
                size_t o = (size_t)row * N + col;
                if (Cf) *(float2*)&Cf[o] = make_float2(v0, v1);
                if (Ch) *(uint32_t*)&Ch[o] = packh2(v0, v1);
            }
        }
    }
}

// ---------------- Flash attention (fp16 mma, register softmax) --------------
#define FSTR 72

struct FaSmem {
    f16 Q[128][FSTR];
    f16 K[64][FSTR];
    f16 Vt[64][FSTR];   // transposed [d][key]
};

__global__ __launch_bounds__(256) void flash_attn(
    const f16* __restrict__ qkv, f16* __restrict__ outp)
{
    extern __shared__ char smem_raw[];
    FaSmem& S = *(FaSmem*)smem_raw;
    const int tid  = threadIdx.x;
    const int lane = tid & 31;
    const int wid  = tid >> 5;
    const int b  = blockIdx.y >> 4, h = blockIdx.y & 15;
    const int q0 = blockIdx.x * 128;

    const int mat = lane >> 3, rin = lane & 7;
    const int a_row_off = (mat & 1) * 8 + rin;
    const int a_col_off = (mat >> 1) * 8;
    const int b_row_off = (mat >> 1) * 8 + rin;
    const int b_col_off = (mat & 1) * 8;

    __half2 sc2 = __floats2half2_rn(0.125f, 0.125f);

    // Q tile with exact x0.125 scale
    for (int idx = tid; idx < 128 * 8; idx += 256) {
        int r = idx >> 3, f = idx & 7;
        size_t go = (size_t)(b*SEQ + q0 + r)*QKVN + h*HD + f*8;
        float4 v = *(const float4*)&qkv[go];
        __half2* pv = (__half2*)&v;
#pragma unroll
        for (int j = 0; j < 4; j++) pv[j] = __hmul2(pv[j], sc2);
        *(float4*)&S.Q[r][f*8] = v;
    }

    float m_[2] = {-1e30f, -1e30f};
    float l_[2] = {0.f, 0.f};
    float o[8][4];
#pragma unroll
    for (int i = 0; i < 8; i++)
#pragma unroll
        for (int j = 0; j < 4; j++) o[i][j] = 0.f;

    for (int kv0 = 0; kv0 < SEQ; kv0 += 64) {
        __syncthreads();
        for (int idx = tid; idx < 64 * 8; idx += 256) {
            int c = idx >> 3, f = idx & 7;
            size_t go = (size_t)(b*SEQ + kv0 + c)*QKVN + h*HD + f*8;
            *(float4*)&S.K[c][f*8] = *(const float4*)&qkv[go + DIM];
            float4 vv = *(const float4*)&qkv[go + 2*DIM];
            const f16* ev = (const f16*)&vv;
#pragma unroll
            for (int j = 0; j < 8; j++) S.Vt[f*8 + j][c] = ev[j];
        }
        __syncthreads();

        // S = Q K^T (warp: 16 q-rows x 64 keys)
        float s[8][4];
#pragma unroll
        for (int i = 0; i < 8; i++)
#pragma unroll
            for (int j = 0; j < 4; j++) s[i][j] = 0.f;
#pragma unroll
        for (int ks = 0; ks < 4; ks++) {
            int kk = ks * 16;
            uint32_t a[4], bq[8][2];
            ldsm_x4(a[0], a[1], a[2], a[3],
                    smem_u32(&S.Q[wid*16 + a_row_off][kk + a_col_off]));
#pragma unroll
            for (int ng = 0; ng < 4; ng++)
                ldsm_x4(bq[ng*2][0], bq[ng*2][1], bq[ng*2+1][0], bq[ng*2+1][1],
                        smem_u32(&S.K[ng*16 + b_row_off][kk + b_col_off]));
#pragma unroll
            for (int ni = 0; ni < 8; ni++)
                mma_f16(s[ni], a, bq[ni]);
        }

        // online softmax in registers
#pragma unroll
        for (int half_ = 0; half_ < 2; half_++) {
            float mloc = -1e30f;
#pragma unroll
            for (int ni = 0; ni < 8; ni++) {
                mloc = fmaxf(mloc, s[ni][half_*2+0]);
                mloc = fmaxf(mloc, s[ni][half_*2+1]);
            }
            mloc = fmaxf(mloc, __shfl_xor_sync(0xffffffffu, mloc, 1));
            mloc = fmaxf(mloc, __shfl_xor_sync(0xffffffffu, mloc, 2));
            float mnew = fmaxf(m_[half_], mloc);
            float alf = __expf(m_[half_] - mnew);
            m_[half_] = mnew;
            float ps = 0.f;
#pragma unroll
            for (int ni = 0; ni < 8; ni++) {
                float p0 = __expf(s[ni][half_*2+0] - mnew);
                float p1 = __expf(s[ni][half_*2+1] - mnew);
                s[ni][half_*2+0] = p0; s[ni][half_*2+1] = p1;
                ps += p0 + p1;
            }
            ps += __shfl_xor_sync(0xffffffffu, ps, 1);
            ps += __shfl_xor_sync(0xffffffffu, ps, 2);
            l_[half_] = l_[half_] * alf + ps;
#pragma unroll
            for (int ni = 0; ni < 8; ni++) {
                o[ni][half_*2+0] *= alf;
                o[ni][half_*2+1] *= alf;
            }
        }

        // O += P V
#pragma unroll
        for (int ks = 0; ks < 4; ks++) {
            uint32_t pa[4];
            pa[0] = packh2(s[2*ks][0],   s[2*ks][1]);
            pa[1] = packh2(s[2*ks][2],   s[2*ks][3]);
            pa[2] = packh2(s[2*ks+1][0], s[2*ks+1][1]);
            pa[3] = packh2(s[2*ks+1][2], s[2*ks+1][3]);
            uint32_t bv[8][2];
#pragma unroll
            for (int ng = 0; ng < 4; ng++)
                ldsm_x4(bv[ng*2][0], bv[ng*2][1], bv[ng*2+1][0], bv[ng*2+1][1],
                        smem_u32(&S.Vt[ng*16 + b_row_off][ks*16 + b_col_off]));
#pragma unroll
            for (int ni = 0; ni < 8; ni++)
                mma_f16(o[ni], pa, bv[ni]);
        }
    }

    float inv0 = 1.f / l_[0], inv1 = 1.f / l_[1];
#pragma unroll
    for (int ni = 0; ni < 8; ni++) {
        int col = ni * 8 + (lane & 3) * 2;
#pragma unroll
        for (int half_ = 0; half_ < 2; half_++) {
            float inv = half_ ? inv1 : inv0;
            int row = q0 + wid * 16 + (lane >> 2) + half_ * 8;
            float v0 = o[ni][half_*2+0] * inv;
            float v1 = o[ni][half_*2+1] * inv;
            size_t base = (size_t)(b*SEQ + row)*DIM + h*HD + col;
            *(uint32_t*)&outp[base] = packh2(v0, v1);
        }
    }
}

// ---------------- residual add + LayerNorm ---------------------------------
__global__ __launch_bounds__(256) void add_ln(
    const float* __restrict__ a, const float* __restrict__ bres,
    const float* __restrict__ g, const float* __restrict__ beta,
    float* __restrict__ out, f16* __restrict__ out_h)
{
    const int row = blockIdx.x;
    const int tid = threadIdx.x;
    float4 av = *(const float4*)&a   [(size_t)row*DIM + tid*4];
    float4 bv = *(const float4*)&bres[(size_t)row*DIM + tid*4];
    float v[4] = {av.x+bv.x, av.y+bv.y, av.z+bv.z, av.w+bv.w};
    float s  = v[0]+v[1]+v[2]+v[3];
    float sq = v[0]*v[0]+v[1]*v[1]+v[2]*v[2]+v[3]*v[3];

    __shared__ float rs[256], rq[256];
    rs[tid] = s; rq[tid] = sq;
    __syncthreads();
    for (int off = 128; off > 0; off >>= 1) {
        if (tid < off) { rs[tid] += rs[tid+off]; rq[tid] += rq[tid+off]; }
        __syncthreads();
    }
    float mean = rs[0] * (1.f/DIM);
    float var  = rq[0] * (1.f/DIM) - mean*mean;
    float rstd = rsqrtf(var + 1e-5f);

    float4 gv = *(const float4*)&g[tid*4];
    float4 ev = *(const float4*)&beta[tid*4];
    float ov[4];
    ov[0] = (v[0]-mean)*rstd*gv.x + ev.x;
    ov[1] = (v[1]-mean)*rstd*gv.y + ev.y;
    ov[2] = (v[2]-mean)*rstd*gv.z + ev.z;
    ov[3] = (v[3]-mean)*rstd*gv.w + ev.w;
    *(float4*)&out[(size_t)row*DIM + tid*4] = make_float4(ov[0],ov[1],ov[2],ov[3]);
    if (out_h) {
        size_t base = (size_t)row*DIM + tid*4;
        *(uint32_t*)&out_h[base]   = packh2(ov[0], ov[1]);
        *(uint32_t*)&out_h[base+2] = packh2(ov[2], ov[3]);
    }
}

// ---------------- launch ---------------------------------------------------
extern "C" void kernel_launch(void* const* d_in, const int* in_sizes, int n_in,
                              void* d_out, int out_size)
{
    (void)in_sizes; (void)n_in; (void)out_size;
    const float* x       = (const float*)d_in[0];
    const float* qkv_w   = (const float*)d_in[1];
    const float* proj_w  = (const float*)d_in[2];
    const float* proj_b  = (const float*)d_in[3];
    const float* ln1_g   = (const float*)d_in[4];
    const float* ln1_b   = (const float*)d_in[5];
    const float* w1      = (const float*)d_in[6];
    const float* b1      = (const float*)d_in[7];
    const float* prelu_a = (const float*)d_in[8];
    const float* w2      = (const float*)d_in[9];
    const float* b2      = (const float*)d_in[10];
    const float* ln2_g   = (const float*)d_in[11];
    const float* ln2_b   = (const float*)d_in[12];
    float* out = (float*)d_out;

    float *x1, *tmp;
    f16 *qkv,*xf,*af,*x1f,*hf,*wq,*wp,*w1f,*w2f;
    cudaGetSymbolAddress((void**)&qkv, g_qkv);
    cudaGetSymbolAddress((void**)&x1,  g_x1);
    cudaGetSymbolAddress((void**)&tmp, g_tmp);
    cudaGetSymbolAddress((void**)&xf,  g_xf);
    cudaGetSymbolAddress((void**)&af,  g_af);
    cudaGetSymbolAddress((void**)&x1f, g_x1f);
    cudaGetSymbolAddress((void**)&hf,  g_hf);
    cudaGetSymbolAddress((void**)&wq,  g_wq);
    cudaGetSymbolAddress((void**)&wp,  g_wp);
    cudaGetSymbolAddress((void**)&w1f, g_w1);
    cudaGetSymbolAddress((void**)&w2f, g_w2);

    const dim3 blk(256);
    const int fasz = (int)sizeof(FaSmem);
    cudaFuncSetAttribute(flash_attn, cudaFuncAttributeMaxDynamicSharedMemorySize, fasz);
    cudaFuncSetAttribute(gemm_f16, cudaFuncAttributeMaxDynamicSharedMemorySize, GEMM_SMEM);

    // converts (input + weights)
    to_f16<<<(MROWS*DIM)/1024, blk>>>(x, xf);
    to_f16<<<(QKVN*DIM)/1024, blk>>>(qkv_w, wq);
    to_f16<<<(DIM*DIM)/1024,  blk>>>(proj_w, wp);
    to_f16<<<(HID*DIM)/1024,  blk>>>(w1, w1f);
    to_f16<<<(DIM*HID)/1024,  blk>>>(w2, w2f);

    // 1) qkv = x @ qkv_w^T -> fp16
    gemm_f16<<<dim3(QKVN/128, MROWS/128), blk, GEMM_SMEM>>>(
        xf, wq, nullptr, nullptr, nullptr, qkv, MROWS, QKVN, DIM);
    // 2) attention -> fp16
    flash_attn<<<dim3(SEQ/128, B_SZ*HEADS), blk, fasz>>>(qkv, af);
    // 3) proj -> tmp fp32
    gemm_f16<<<dim3(DIM/128, MROWS/128), blk, GEMM_SMEM>>>(
        af, wp, proj_b, nullptr, tmp, nullptr, MROWS, DIM, DIM);
    // 4) x1 = LN(x + proj) fp32 + fp16
    add_ln<<<MROWS, blk>>>(x, tmp, ln1_g, ln1_b, x1, x1f);
    // 5) h = PReLU(x1 @ w1^T + b1) -> fp16
    gemm_f16<<<dim3(HID/128, MROWS/128), blk, GEMM_SMEM>>>(
        x1f, w1f, b1, prelu_a, nullptr, hf, MROWS, HID, DIM);
    // 6) h2 = h @ w2^T + b2 -> tmp fp32
    gemm_f16<<<dim3(DIM/128, MROWS/128), blk, GEMM_SMEM>>>(
        hf, w2f, b2, nullptr, tmp, nullptr, MROWS, DIM, HID);
    // 7) out = LN(x1 + h2)
    add_ln<<<MROWS, blk>>>(x1, tmp, ln2_g, ln2_b, out, nullptr);
}